// round 3
// baseline (speedup 1.0000x reference)
#include <cuda_runtime.h>
#include <math.h>
#include <float.h>

// Problem constants
#define Bd  2
#define Sd  2048
#define Dd  2048
#define Hd  16
#define HDd 128
#define Md  (Bd*Sd)   // 4096 rows of x flattened

// GEMM tiling
#define BM 128
#define BN 128
#define BK 16
#define TM 8
#define TN 8
#define NTHREADS 256
#define SPAD 4        // smem row padding: keeps float4 aligned, stores <=2-way conflict

// Scratch (allocation-free rule: __device__ globals)
__device__ float g_q[(size_t)Bd*Hd*Sd*HDd];        //  32 MB: Q in [B,H,S,HD]
__device__ float g_scores[(size_t)Bd*Hd*Sd*Sd];    // 512 MB: scores / probs per (b,h)
__device__ float g_om[(size_t)Bd*Sd*Dd];           //  32 MB: merged attention output [B,S,D]

enum { EPI_PLAIN = 0, EPI_SPLIT = 1, EPI_SCORES = 2, EPI_AV = 3 };

// C = A * B^T (BT=true, B is [N,K] row-major) or A * B (BT=false, B is [K,N] row-major)
// All of M, N, K are multiples of the tile sizes for every launch in this problem.
template<int EPI, bool BT>
__global__ __launch_bounds__(NTHREADS, 2)
void gemm_kernel(const float* __restrict__ A, const float* __restrict__ Bm,
                 float* __restrict__ C,
                 int M, int N, int K,
                 long long sA, long long sB, float scale)
{
    __shared__ float As[BK][BM + SPAD];
    __shared__ float Bs[BK][BN + SPAD];

    const int bx = blockIdx.x, by = blockIdx.y, bz = blockIdx.z;

    // Causal block skip for the scores GEMM: column tile entirely above diagonal.
    if (EPI == EPI_SCORES && bx > by) return;

    A  += (size_t)bz * sA;
    Bm += (size_t)bz * sB;

    const int m0 = by * BM;
    const int n0 = bx * BN;
    const int tid = threadIdx.x;
    const int tx = tid & 15;
    const int ty = tid >> 4;

    // For P*V: rows m0..m0+127 only need k <= m0+127 (P zeroed above diagonal anyway).
    int kend = K;
    if (EPI == EPI_AV) kend = (K < m0 + BM) ? K : (m0 + BM);

    float acc[TM][TN];
    #pragma unroll
    for (int i = 0; i < TM; ++i)
        #pragma unroll
        for (int j = 0; j < TN; ++j)
            acc[i][j] = 0.0f;

    for (int k0 = 0; k0 < kend; k0 += BK) {
        // ---- stage A tile (transpose into As[k][m]) ----
        #pragma unroll
        for (int it = 0; it < (BM*BK)/(4*NTHREADS); ++it) {
            int i   = tid + it * NTHREADS;      // 0..511
            int row = i >> 2;                   // BK/4 = 4 float4 per row
            int kc  = (i & 3) << 2;
            const float4 v = *reinterpret_cast<const float4*>(
                &A[(size_t)(m0 + row) * K + k0 + kc]);
            As[kc+0][row] = v.x; As[kc+1][row] = v.y;
            As[kc+2][row] = v.z; As[kc+3][row] = v.w;
        }
        // ---- stage B tile ----
        if (BT) {
            #pragma unroll
            for (int it = 0; it < (BN*BK)/(4*NTHREADS); ++it) {
                int i   = tid + it * NTHREADS;
                int row = i >> 2;
                int kc  = (i & 3) << 2;
                const float4 v = *reinterpret_cast<const float4*>(
                    &Bm[(size_t)(n0 + row) * K + k0 + kc]);
                Bs[kc+0][row] = v.x; Bs[kc+1][row] = v.y;
                Bs[kc+2][row] = v.z; Bs[kc+3][row] = v.w;
            }
        } else {
            #pragma unroll
            for (int it = 0; it < (BN*BK)/(4*NTHREADS); ++it) {
                int i  = tid + it * NTHREADS;
                int kk = i >> 5;                 // BN/4 = 32 float4 per k-row
                int nc = (i & 31) << 2;
                *reinterpret_cast<float4*>(&Bs[kk][nc]) =
                    *reinterpret_cast<const float4*>(
                        &Bm[(size_t)(k0 + kk) * N + n0 + nc]);
            }
        }
        __syncthreads();

        // ---- 128x128x16 register-blocked FMA ----
        #pragma unroll
        for (int kk = 0; kk < BK; ++kk) {
            float a[TM], b[TN];
            *reinterpret_cast<float4*>(&a[0]) = *reinterpret_cast<const float4*>(&As[kk][ty*TM    ]);
            *reinterpret_cast<float4*>(&a[4]) = *reinterpret_cast<const float4*>(&As[kk][ty*TM + 4]);
            *reinterpret_cast<float4*>(&b[0]) = *reinterpret_cast<const float4*>(&Bs[kk][tx*TN    ]);
            *reinterpret_cast<float4*>(&b[4]) = *reinterpret_cast<const float4*>(&Bs[kk][tx*TN + 4]);
            #pragma unroll
            for (int i = 0; i < TM; ++i)
                #pragma unroll
                for (int j = 0; j < TN; ++j)
                    acc[i][j] = fmaf(a[i], b[j], acc[i][j]);
        }
        __syncthreads();
    }

    // ---- epilogue ----
    #pragma unroll
    for (int i = 0; i < TM; ++i) {
        const int m = m0 + ty*TM + i;
        #pragma unroll
        for (int j = 0; j < TN; ++j) {
            const int n = n0 + tx*TN + j;
            const float val = acc[i][j];
            if (EPI == EPI_PLAIN) {
                C[(size_t)m * N + n] = val;
            } else if (EPI == EPI_SPLIT) {
                // [B*S, D] -> [B,H,S,HD]
                const int b = m >> 11, s = m & (Sd - 1);
                const int h = n >> 7,  hd = n & (HDd - 1);
                C[(((size_t)(b*Hd + h))*Sd + s)*HDd + hd] = val;
            } else if (EPI == EPI_SCORES) {
                C[(size_t)bz*Sd*Sd + (size_t)m*N + n] = val * scale;
            } else { // EPI_AV: merge heads -> [B,S,D]
                const int b = bz >> 4, h = bz & 15;
                C[((size_t)(b*Sd + m))*Dd + h*HDd + n] = val;
            }
        }
    }
}

// In-place causal softmax over rows of g_scores. Row i uses entries [0, i];
// entries (i, S) are written as exact zeros so P*V needs no mask.
__global__ void softmax_causal_kernel(float* __restrict__ P)
{
    const int row = blockIdx.x;
    const int bh  = blockIdx.y;
    float* p = P + (size_t)bh*Sd*Sd + (size_t)row*Sd;
    const int n = row + 1;
    const int tid = threadIdx.x;

    __shared__ float red[256];

    float v[8];
    int cnt = 0;
    float mx = -FLT_MAX;
    for (int j = tid; j < n; j += 256) {
        float x = p[j];
        v[cnt++] = x;
        mx = fmaxf(mx, x);
    }
    red[tid] = mx; __syncthreads();
    #pragma unroll
    for (int s = 128; s > 0; s >>= 1) {
        if (tid < s) red[tid] = fmaxf(red[tid], red[tid + s]);
        __syncthreads();
    }
    mx = red[0];
    __syncthreads();

    float sum = 0.0f;
    for (int c = 0; c < cnt; ++c) {
        v[c] = expf(v[c] - mx);
        sum += v[c];
    }
    red[tid] = sum; __syncthreads();
    #pragma unroll
    for (int s = 128; s > 0; s >>= 1) {
        if (tid < s) red[tid] += red[tid + s];
        __syncthreads();
    }
    const float inv = 1.0f / red[0];

    cnt = 0;
    for (int j = tid; j < Sd; j += 256) {
        p[j] = (j < n) ? v[cnt++] * inv : 0.0f;
    }
}

extern "C" void kernel_launch(void* const* d_in, const int* in_sizes, int n_in,
                              void* d_out, int out_size)
{
    const float* x  = (const float*)d_in[0];
    const float* Wq = (const float*)d_in[1];
    const float* Wk = (const float*)d_in[2];
    const float* Wv = (const float*)d_in[3];
    const float* Wo = (const float*)d_in[4];

    // Output tuple (out, k, v), flattened in order.
    float* out  = (float*)d_out;
    float* kout = out  + (size_t)Bd*Sd*Dd;   // [B,H,S,HD]
    float* vout = kout + (size_t)Bd*Sd*Dd;   // [B,H,S,HD]

    float *qp, *sp, *omp_;
    cudaGetSymbolAddress((void**)&qp,   g_q);
    cudaGetSymbolAddress((void**)&sp,   g_scores);
    cudaGetSymbolAddress((void**)&omp_, g_om);

    const dim3 blk(NTHREADS);

    // 1) QKV projections: [4096,2048] @ W^T -> split-head layout
    const dim3 gA(Dd/BN, Md/BM, 1);
    gemm_kernel<EPI_SPLIT,  true><<<gA, blk>>>(x, Wq, qp,   Md, Dd, Dd, 0, 0, 1.0f);
    gemm_kernel<EPI_SPLIT,  true><<<gA, blk>>>(x, Wk, kout, Md, Dd, Dd, 0, 0, 1.0f);
    gemm_kernel<EPI_SPLIT,  true><<<gA, blk>>>(x, Wv, vout, Md, Dd, Dd, 0, 0, 1.0f);

    // 2) Scores: per (b,h): Q[S,HD] @ K[S,HD]^T * scale (upper-triangle blocks skipped)
    const dim3 gB(Sd/BN, Sd/BM, Bd*Hd);
    const float scale = 1.0f / sqrtf((float)HDd);
    gemm_kernel<EPI_SCORES, true><<<gB, blk>>>(qp, kout, sp, Sd, Sd, HDd,
                                               (long long)Sd*HDd, (long long)Sd*HDd, scale);

    // 3) Causal softmax, in place
    softmax_causal_kernel<<<dim3(Sd, Bd*Hd), 256>>>(sp);

    // 4) P @ V (k-clamped per row tile), merge heads -> [B,S,D]
    const dim3 gD(HDd/BN, Sd/BM, Bd*Hd);
    gemm_kernel<EPI_AV,    false><<<gD, blk>>>(sp, vout, omp_, Sd, HDd, Sd,
                                               (long long)Sd*Sd, (long long)Sd*HDd, 1.0f);

    // 5) Output projection: [4096,2048] @ Wo^T -> out
    const dim3 gE(Dd/BN, Md/BM, 1);
    gemm_kernel<EPI_PLAIN, true><<<gE, blk>>>(omp_, Wo, out, Md, Dd, Dd, 0, 0, 1.0f);
}

// round 5
// speedup vs baseline: 2.8391x; 2.8391x over previous
#include <cuda_runtime.h>
#include <cuda_bf16.h>
#include <math.h>
#include <float.h>
#include <stdint.h>

#define Bd  2
#define Sd  2048
#define Dd  2048
#define Hd  16
#define HDd 128
#define Md  (Bd*Sd)
#define BHd (Bd*Hd)

typedef __nv_bfloat16 bf16;

// ---------------- scratch (__device__ globals; allocation-free rule) ----------------
__device__ bf16 g_xh[(size_t)Md*Dd],  g_xl[(size_t)Md*Dd];
__device__ bf16 g_wqh[(size_t)Dd*Dd], g_wql[(size_t)Dd*Dd];
__device__ bf16 g_wkh[(size_t)Dd*Dd], g_wkl[(size_t)Dd*Dd];
__device__ bf16 g_wvh[(size_t)Dd*Dd], g_wvl[(size_t)Dd*Dd];
__device__ bf16 g_woh[(size_t)Dd*Dd], g_wol[(size_t)Dd*Dd];
__device__ bf16 g_qh[(size_t)BHd*Sd*HDd], g_ql[(size_t)BHd*Sd*HDd];
__device__ bf16 g_kh[(size_t)BHd*Sd*HDd], g_kl[(size_t)BHd*Sd*HDd];
__device__ bf16 g_vth[(size_t)BHd*HDd*Sd], g_vtl[(size_t)BHd*HDd*Sd];  // V^T: [HD][S]
__device__ float g_s[(size_t)BHd*Sd*Sd];                                // fp32 scores
__device__ bf16 g_ph[(size_t)BHd*Sd*Sd], g_pl[(size_t)BHd*Sd*Sd];      // probs hi/lo
__device__ bf16 g_omh[(size_t)Md*Dd], g_oml[(size_t)Md*Dd];            // attn out hi/lo

// ---------------- PTX helpers (sm_80-class only; no tcgen05) ----------------
__device__ __forceinline__ uint32_t smem_u32(const void* p) {
    uint32_t a;
    asm("{ .reg .u64 t; cvta.to.shared.u64 t, %1; cvt.u32.u64 %0, t; }" : "=r"(a) : "l"(p));
    return a;
}
__device__ __forceinline__ void cpa16(uint32_t dst, const void* src) {
    asm volatile("cp.async.cg.shared.global [%0], [%1], 16;" :: "r"(dst), "l"(src) : "memory");
}
#define CP_COMMIT() asm volatile("cp.async.commit_group;" ::: "memory")
#define CP_WAIT0()  asm volatile("cp.async.wait_group 0;" ::: "memory")
#define CP_WAIT1()  asm volatile("cp.async.wait_group 1;" ::: "memory")

__device__ __forceinline__ void ldsm_x4(uint32_t (&r)[4], uint32_t addr) {
    asm volatile("ldmatrix.sync.aligned.m8n8.x4.shared.b16 {%0,%1,%2,%3}, [%4];"
                 : "=r"(r[0]), "=r"(r[1]), "=r"(r[2]), "=r"(r[3]) : "r"(addr));
}
__device__ __forceinline__ void mma16816(float (&d)[4], const uint32_t (&a)[4],
                                         uint32_t b0, uint32_t b1) {
    asm volatile("mma.sync.aligned.m16n8k16.row.col.f32.bf16.bf16.f32 "
                 "{%0,%1,%2,%3}, {%4,%5,%6,%7}, {%8,%9}, {%0,%1,%2,%3};"
                 : "+f"(d[0]), "+f"(d[1]), "+f"(d[2]), "+f"(d[3])
                 : "r"(a[0]), "r"(a[1]), "r"(a[2]), "r"(a[3]), "r"(b0), "r"(b1));
}

// SW128-style swizzle on a [128 rows x 128 bytes] tile
#define SWZ(x) ((x) ^ (((x) >> 3) & 0x70))

enum { EPI_Q = 0, EPI_K = 1, EPI_V = 2, EPI_SC = 3, EPI_AV = 4, EPI_OUT = 5 };

#define TILE_B   16384                 // one 128x64 bf16 tile
#define BUF_B    (4*TILE_B)            // Ah,Al,Bh,Bl
#define GSMEM    (1024 + 2*BUF_B)      // align pad + double buffer = 132096 B

__device__ __forceinline__ void split_pair(float v0, float v1,
                                           __nv_bfloat162& h2, __nv_bfloat162& l2) {
    bf16 h0 = __float2bfloat16(v0), h1 = __float2bfloat16(v1);
    h2 = __halves2bfloat162(h0, h1);
    l2 = __halves2bfloat162(__float2bfloat16(v0 - __bfloat162float(h0)),
                            __float2bfloat16(v1 - __bfloat162float(h1)));
}

// ---- GEMM: C[128x128 tile] = (Ah+Al)·(Bh+Bl)^T via 3-pass bf16 mma.sync ----
// A: [Mrows x K] k-major (ldA), B: [Nrows x K] k-major (ldB). K multiple of 64.
template<int EPI>
__global__ __launch_bounds__(256, 1)
void tc_gemm(const bf16* __restrict__ Ah, const bf16* __restrict__ Al,
             const bf16* __restrict__ Bh, const bf16* __restrict__ Bl,
             float* __restrict__ Cf, bf16* __restrict__ Ch, bf16* __restrict__ Cl,
             int Kdim, int ldA, int ldB, long long sA, long long sB, float scale)
{
    extern __shared__ char smem[];
    const int bx = blockIdx.x, by = blockIdx.y, bz = blockIdx.z;
    if (EPI == EPI_SC && bx > by) return;   // causal block skip

    const int tid = threadIdx.x, wid = tid >> 5, lane = tid & 31;
    const int wm = wid >> 2, wn = wid & 3;  // 2x4 warp grid: 64x32 per warp
    const int m0 = by * 128, n0 = bx * 128;

    Ah += (size_t)bz * sA;  Al += (size_t)bz * sA;
    Bh += (size_t)bz * sB;  Bl += (size_t)bz * sB;

    int kend = Kdim;
    if (EPI == EPI_AV) kend = (Kdim < m0 + 128) ? Kdim : (m0 + 128);
    const int NC = kend >> 6;

    const uint32_t sb = (smem_u32(smem) + 1023) & ~1023u;

    // staging coords: 4 x 16B pieces per thread per 128x64 tile
    int pr[4]; uint32_t poff[4];
    #pragma unroll
    for (int t = 0; t < 4; t++) {
        int i = tid + t * 256;
        pr[t] = i >> 3;
        int pc = (i & 7) * 8;                         // bf16 col
        poff[t] = SWZ((uint32_t)(pr[t] * 128 + pc * 2));
    }
    auto CPAC = [&](int c, int buf) {
        const int k0 = c * 64;
        const uint32_t b0 = sb + buf * BUF_B;
        #pragma unroll
        for (int t = 0; t < 4; t++) {
            int pc = ((tid + t * 256) & 7) * 8;
            const size_t ao = (size_t)(m0 + pr[t]) * ldA + k0 + pc;
            const size_t bo = (size_t)(n0 + pr[t]) * ldB + k0 + pc;
            cpa16(b0              + poff[t], Ah + ao);
            cpa16(b0 +   TILE_B   + poff[t], Al + ao);
            cpa16(b0 + 2*TILE_B   + poff[t], Bh + bo);
            cpa16(b0 + 3*TILE_B   + poff[t], Bl + bo);
        }
    };

    // per-lane ldmatrix address components (swizzle folds to XOR on 16B-unit bits)
    const int aRow  = lane & 15;                       // row within 16-row A block
    const uint32_t aHi = ((lane >> 4) & 1) * 16;       // 16B half of k16
    const uint32_t aXor = (uint32_t)((aRow & 7) << 4);
    uint32_t aRowOff[4];
    #pragma unroll
    for (int mt = 0; mt < 4; mt++)
        aRowOff[mt] = (uint32_t)((wm * 64 + mt * 16 + aRow) * 128);

    const int bN   = (lane & 7) + ((lane >> 4) & 1) * 8;   // n within 16-row B block
    const uint32_t bHi = ((lane >> 3) & 1) * 16;
    const uint32_t bXor = (uint32_t)((bN & 7) << 4);
    uint32_t bRowOff[2];
    #pragma unroll
    for (int ntp = 0; ntp < 2; ntp++)
        bRowOff[ntp] = (uint32_t)((wn * 32 + ntp * 16 + bN) * 128);

    float acc[4][4][4];
    #pragma unroll
    for (int i = 0; i < 4; i++)
        #pragma unroll
        for (int j = 0; j < 4; j++)
            #pragma unroll
            for (int q = 0; q < 4; q++) acc[i][j][q] = 0.0f;

    CPAC(0, 0); CP_COMMIT();

    for (int c = 0; c < NC; c++) {
        const int buf = c & 1;
        if (c + 1 < NC) { CPAC(c + 1, buf ^ 1); CP_COMMIT(); CP_WAIT1(); }
        else            { CP_WAIT0(); }
        __syncthreads();

        const uint32_t tAh = sb + buf * BUF_B;
        const uint32_t tAl = tAh + TILE_B;
        const uint32_t tBh = tAh + 2 * TILE_B;
        const uint32_t tBl = tAh + 3 * TILE_B;

        #pragma unroll
        for (int kb = 0; kb < 4; kb++) {
            const uint32_t akc = (uint32_t)(kb * 32) + aHi;
            const uint32_t bkc = (uint32_t)(kb * 32) + bHi;

            uint32_t ah[4][4], al[4][4];
            #pragma unroll
            for (int mt = 0; mt < 4; mt++) {
                const uint32_t off = aRowOff[mt] + (akc ^ aXor);
                ldsm_x4(ah[mt], tAh + off);
                ldsm_x4(al[mt], tAl + off);
            }
            uint32_t bh[2][4], bl[2][4];
            #pragma unroll
            for (int ntp = 0; ntp < 2; ntp++) {
                const uint32_t off = bRowOff[ntp] + (bkc ^ bXor);
                ldsm_x4(bh[ntp], tBh + off);
                ldsm_x4(bl[ntp], tBl + off);
            }
            #pragma unroll
            for (int mt = 0; mt < 4; mt++)
                #pragma unroll
                for (int nt = 0; nt < 4; nt++) {
                    const int p = nt >> 1, q = (nt & 1) * 2;
                    mma16816(acc[mt][nt], ah[mt], bh[p][q], bh[p][q+1]);  // hi*hi
                    mma16816(acc[mt][nt], ah[mt], bl[p][q], bl[p][q+1]);  // hi*lo
                    mma16816(acc[mt][nt], al[mt], bh[p][q], bh[p][q+1]);  // lo*hi
                }
        }
        __syncthreads();
    }

    // ---------------- epilogue (register fragments) ----------------
    const int r0 = lane >> 2;
    const int cp2 = (lane & 3) * 2;

    #pragma unroll
    for (int mt = 0; mt < 4; mt++) {
        #pragma unroll
        for (int nt = 0; nt < 4; nt++) {
            const float* cc = acc[mt][nt];
            const int gmA = m0 + wm * 64 + mt * 16 + r0;
            const int gmB = gmA + 8;
            const int nl  = wn * 32 + nt * 8 + cp2;   // col within 128-tile
            const int gn  = n0 + nl;

            if (EPI == EPI_SC) {
                float* dst = Cf + (size_t)bz * Sd * Sd;
                *reinterpret_cast<float2*>(dst + (size_t)gmA * Sd + gn) =
                    make_float2(cc[0] * scale, cc[1] * scale);
                *reinterpret_cast<float2*>(dst + (size_t)gmB * Sd + gn) =
                    make_float2(cc[2] * scale, cc[3] * scale);
            } else if (EPI == EPI_OUT) {
                *reinterpret_cast<float2*>(Cf + (size_t)gmA * Dd + gn) = make_float2(cc[0], cc[1]);
                *reinterpret_cast<float2*>(Cf + (size_t)gmB * Dd + gn) = make_float2(cc[2], cc[3]);
            } else if (EPI == EPI_AV) {
                const int b = bz >> 4, h = bz & 15;
                __nv_bfloat162 h2, l2;
                size_t baseA = ((size_t)(b * Sd + gmA)) * Dd + h * HDd + nl;
                size_t baseB = ((size_t)(b * Sd + gmB)) * Dd + h * HDd + nl;
                split_pair(cc[0], cc[1], h2, l2);
                *reinterpret_cast<__nv_bfloat162*>(Ch + baseA) = h2;
                *reinterpret_cast<__nv_bfloat162*>(Cl + baseA) = l2;
                split_pair(cc[2], cc[3], h2, l2);
                *reinterpret_cast<__nv_bfloat162*>(Ch + baseB) = h2;
                *reinterpret_cast<__nv_bfloat162*>(Cl + baseB) = l2;
            } else {
                // projections: n-tile == head bx
                const int h = bx;
                #pragma unroll
                for (int half = 0; half < 2; half++) {
                    const int gm = half ? gmB : gmA;
                    const float v0 = cc[half * 2], v1 = cc[half * 2 + 1];
                    const int b = gm >> 11, s = gm & (Sd - 1);
                    const size_t base = (((size_t)(b * Hd + h)) * Sd + s) * HDd + nl;
                    if (EPI == EPI_K || EPI == EPI_V)
                        *reinterpret_cast<float2*>(Cf + base) = make_float2(v0, v1);
                    if (EPI == EPI_V) {
                        // transposed bf16 scratch: [b,h][hd][s]
                        const size_t ti = (((size_t)(b * Hd + h)) * HDd + nl) * Sd + s;
                        bf16 h0 = __float2bfloat16(v0), h1 = __float2bfloat16(v1);
                        Ch[ti]      = h0;
                        Ch[ti + Sd] = h1;
                        Cl[ti]      = __float2bfloat16(v0 - __bfloat162float(h0));
                        Cl[ti + Sd] = __float2bfloat16(v1 - __bfloat162float(h1));
                    } else {
                        __nv_bfloat162 h2, l2;
                        split_pair(v0, v1, h2, l2);
                        *reinterpret_cast<__nv_bfloat162*>(Ch + base) = h2;
                        *reinterpret_cast<__nv_bfloat162*>(Cl + base) = l2;
                    }
                }
            }
        }
    }
}

// ---------------- causal softmax: fp32 scores -> bf16 hi/lo probs ----------------
__global__ void softmax_kernel(const float* __restrict__ S,
                               bf16* __restrict__ Ph, bf16* __restrict__ Pl)
{
    const int row = blockIdx.x, bh = blockIdx.y, tid = threadIdx.x;
    const float* p = S + (size_t)bh * Sd * Sd + (size_t)row * Sd;
    bf16* ph = Ph + (size_t)bh * Sd * Sd + (size_t)row * Sd;
    bf16* pl = Pl + (size_t)bh * Sd * Sd + (size_t)row * Sd;
    const int n = row + 1;
    const int kmax = ((row >> 7) + 1) << 7;   // zero out to 128-block boundary (AV clamp)

    __shared__ float red[256];
    float v[8]; int cnt = 0; float mx = -FLT_MAX;
    for (int j = tid; j < n; j += 256) { float x = p[j]; v[cnt++] = x; mx = fmaxf(mx, x); }
    red[tid] = mx; __syncthreads();
    #pragma unroll
    for (int s2 = 128; s2 > 0; s2 >>= 1) { if (tid < s2) red[tid] = fmaxf(red[tid], red[tid + s2]); __syncthreads(); }
    mx = red[0]; __syncthreads();

    float sum = 0.0f;
    for (int c = 0; c < cnt; c++) { v[c] = expf(v[c] - mx); sum += v[c]; }
    red[tid] = sum; __syncthreads();
    #pragma unroll
    for (int s2 = 128; s2 > 0; s2 >>= 1) { if (tid < s2) red[tid] += red[tid + s2]; __syncthreads(); }
    const float inv = 1.0f / red[0];

    cnt = 0;
    for (int j = tid; j < kmax; j += 256) {
        float val = (j < n) ? v[cnt++] * inv : 0.0f;
        bf16 hh = __float2bfloat16(val);
        ph[j] = hh;
        pl[j] = __float2bfloat16(val - __bfloat162float(hh));
    }
}

// ---------------- fp32 -> (bf16 hi, bf16 lo) split ----------------
__global__ void split_kernel(const float4* __restrict__ in,
                             __nv_bfloat162* __restrict__ hi, __nv_bfloat162* __restrict__ lo,
                             int n4)
{
    int i = blockIdx.x * 256 + threadIdx.x;
    if (i >= n4) return;
    float4 x = in[i];
    __nv_bfloat162 h2, l2;
    split_pair(x.x, x.y, h2, l2); hi[2*i]   = h2; lo[2*i]   = l2;
    split_pair(x.z, x.w, h2, l2); hi[2*i+1] = h2; lo[2*i+1] = l2;
}

extern "C" void kernel_launch(void* const* d_in, const int* in_sizes, int n_in,
                              void* d_out, int out_size)
{
    const float* x  = (const float*)d_in[0];
    const float* Wq = (const float*)d_in[1];
    const float* Wk = (const float*)d_in[2];
    const float* Wv = (const float*)d_in[3];
    const float* Wo = (const float*)d_in[4];

    float* out  = (float*)d_out;
    float* kout = out  + (size_t)Md * Dd;
    float* vout = kout + (size_t)Md * Dd;

    bf16 *xh,*xl,*wqh,*wql,*wkh,*wkl,*wvh,*wvl,*woh,*wol;
    bf16 *qh,*ql,*kh,*kl,*vth,*vtl,*pph,*ppl,*omh,*oml;
    float* sp;
    cudaGetSymbolAddress((void**)&xh, g_xh);   cudaGetSymbolAddress((void**)&xl, g_xl);
    cudaGetSymbolAddress((void**)&wqh, g_wqh); cudaGetSymbolAddress((void**)&wql, g_wql);
    cudaGetSymbolAddress((void**)&wkh, g_wkh); cudaGetSymbolAddress((void**)&wkl, g_wkl);
    cudaGetSymbolAddress((void**)&wvh, g_wvh); cudaGetSymbolAddress((void**)&wvl, g_wvl);
    cudaGetSymbolAddress((void**)&woh, g_woh); cudaGetSymbolAddress((void**)&wol, g_wol);
    cudaGetSymbolAddress((void**)&qh, g_qh);   cudaGetSymbolAddress((void**)&ql, g_ql);
    cudaGetSymbolAddress((void**)&kh, g_kh);   cudaGetSymbolAddress((void**)&kl, g_kl);
    cudaGetSymbolAddress((void**)&vth, g_vth); cudaGetSymbolAddress((void**)&vtl, g_vtl);
    cudaGetSymbolAddress((void**)&pph, g_ph);  cudaGetSymbolAddress((void**)&ppl, g_pl);
    cudaGetSymbolAddress((void**)&omh, g_omh); cudaGetSymbolAddress((void**)&oml, g_oml);
    cudaGetSymbolAddress((void**)&sp, g_s);

    cudaFuncSetAttribute(tc_gemm<EPI_Q>,   cudaFuncAttributeMaxDynamicSharedMemorySize, GSMEM);
    cudaFuncSetAttribute(tc_gemm<EPI_K>,   cudaFuncAttributeMaxDynamicSharedMemorySize, GSMEM);
    cudaFuncSetAttribute(tc_gemm<EPI_V>,   cudaFuncAttributeMaxDynamicSharedMemorySize, GSMEM);
    cudaFuncSetAttribute(tc_gemm<EPI_SC>,  cudaFuncAttributeMaxDynamicSharedMemorySize, GSMEM);
    cudaFuncSetAttribute(tc_gemm<EPI_AV>,  cudaFuncAttributeMaxDynamicSharedMemorySize, GSMEM);
    cudaFuncSetAttribute(tc_gemm<EPI_OUT>, cudaFuncAttributeMaxDynamicSharedMemorySize, GSMEM);

    // 0) split inputs into bf16 hi/lo
    split_kernel<<<(Md*Dd/4 + 255)/256, 256>>>((const float4*)x,  (__nv_bfloat162*)xh,  (__nv_bfloat162*)xl,  Md*Dd/4);
    split_kernel<<<(Dd*Dd/4 + 255)/256, 256>>>((const float4*)Wq, (__nv_bfloat162*)wqh, (__nv_bfloat162*)wql, Dd*Dd/4);
    split_kernel<<<(Dd*Dd/4 + 255)/256, 256>>>((const float4*)Wk, (__nv_bfloat162*)wkh, (__nv_bfloat162*)wkl, Dd*Dd/4);
    split_kernel<<<(Dd*Dd/4 + 255)/256, 256>>>((const float4*)Wv, (__nv_bfloat162*)wvh, (__nv_bfloat162*)wvl, Dd*Dd/4);
    split_kernel<<<(Dd*Dd/4 + 255)/256, 256>>>((const float4*)Wo, (__nv_bfloat162*)woh, (__nv_bfloat162*)wol, Dd*Dd/4);

    const float scale = 1.0f / sqrtf((float)HDd);
    dim3 blk(256);

    // 1) QKV projections (NT): C = x · W^T, fused split-head + hi/lo epilogues
    dim3 gP(Dd/128, Md/128, 1);
    tc_gemm<EPI_Q><<<gP, blk, GSMEM>>>(xh, xl, wqh, wql, nullptr, qh, ql, Dd, Dd, Dd, 0, 0, 1.0f);
    tc_gemm<EPI_K><<<gP, blk, GSMEM>>>(xh, xl, wkh, wkl, kout,   kh, kl, Dd, Dd, Dd, 0, 0, 1.0f);
    tc_gemm<EPI_V><<<gP, blk, GSMEM>>>(xh, xl, wvh, wvl, vout,   vth, vtl, Dd, Dd, Dd, 0, 0, 1.0f);

    // 2) scores (NT, causal block-skip): Q · K^T * scale
    dim3 gS(Sd/128, Sd/128, BHd);
    tc_gemm<EPI_SC><<<gS, blk, GSMEM>>>(qh, ql, kh, kl, sp, nullptr, nullptr,
                                        HDd, HDd, HDd,
                                        (long long)Sd*HDd, (long long)Sd*HDd, scale);

    // 3) softmax (fp32 in, bf16 hi/lo out, zeros to block boundary)
    softmax_kernel<<<dim3(Sd, BHd), 256>>>(sp, pph, ppl);

    // 4) P · V (k-clamped per row tile), via V^T so B is k-major
    dim3 gAV(1, Sd/128, BHd);
    tc_gemm<EPI_AV><<<gAV, blk, GSMEM>>>(pph, ppl, vth, vtl, nullptr, omh, oml,
                                         Sd, Sd, Sd,
                                         (long long)Sd*Sd, (long long)HDd*Sd, 1.0f);

    // 5) output projection (NT) -> fp32 out
    dim3 gO(Dd/128, Md/128, 1);
    tc_gemm<EPI_OUT><<<gO, blk, GSMEM>>>(omh, oml, woh, wol, out, nullptr, nullptr,
                                         Dd, Dd, Dd, 0, 0, 1.0f);
}

// round 6
// speedup vs baseline: 2.9138x; 1.0263x over previous
#include <cuda_runtime.h>
#include <cuda_bf16.h>
#include <math.h>
#include <float.h>
#include <stdint.h>

#define Bd  2
#define Sd  2048
#define Dd  2048
#define Hd  16
#define HDd 128
#define Md  (Bd*Sd)
#define BHd (Bd*Hd)

typedef __nv_bfloat16 bf16;

// ---------------- scratch (__device__ globals; allocation-free rule) ----------------
__device__ bf16 g_xh[(size_t)Md*Dd],  g_xl[(size_t)Md*Dd];
__device__ bf16 g_wqh[(size_t)Dd*Dd], g_wql[(size_t)Dd*Dd];
__device__ bf16 g_wkh[(size_t)Dd*Dd], g_wkl[(size_t)Dd*Dd];
__device__ bf16 g_wvh[(size_t)Dd*Dd], g_wvl[(size_t)Dd*Dd];
__device__ bf16 g_woh[(size_t)Dd*Dd], g_wol[(size_t)Dd*Dd];
__device__ bf16 g_qh[(size_t)BHd*Sd*HDd], g_ql[(size_t)BHd*Sd*HDd];
__device__ bf16 g_kh[(size_t)BHd*Sd*HDd], g_kl[(size_t)BHd*Sd*HDd];
__device__ bf16 g_vth[(size_t)BHd*HDd*Sd], g_vtl[(size_t)BHd*HDd*Sd];  // V^T: [HD][S]
__device__ float g_s[(size_t)BHd*Sd*Sd];                                // fp32 scores
__device__ bf16 g_ph[(size_t)BHd*Sd*Sd], g_pl[(size_t)BHd*Sd*Sd];      // probs hi/lo
__device__ bf16 g_omh[(size_t)Md*Dd], g_oml[(size_t)Md*Dd];            // attn out hi/lo

// ---------------- PTX helpers (sm_80-class only) ----------------
__device__ __forceinline__ uint32_t smem_u32(const void* p) {
    uint32_t a;
    asm("{ .reg .u64 t; cvta.to.shared.u64 t, %1; cvt.u32.u64 %0, t; }" : "=r"(a) : "l"(p));
    return a;
}
__device__ __forceinline__ void cpa16(uint32_t dst, const void* src) {
    asm volatile("cp.async.cg.shared.global [%0], [%1], 16;" :: "r"(dst), "l"(src) : "memory");
}
#define CP_COMMIT() asm volatile("cp.async.commit_group;" ::: "memory")
#define CP_WAIT0()  asm volatile("cp.async.wait_group 0;" ::: "memory")
#define CP_WAIT1()  asm volatile("cp.async.wait_group 1;" ::: "memory")

__device__ __forceinline__ void ldsm_x4(uint32_t (&r)[4], uint32_t addr) {
    asm volatile("ldmatrix.sync.aligned.m8n8.x4.shared.b16 {%0,%1,%2,%3}, [%4];"
                 : "=r"(r[0]), "=r"(r[1]), "=r"(r[2]), "=r"(r[3]) : "r"(addr));
}
__device__ __forceinline__ void mma16816(float (&d)[4], const uint32_t (&a)[4],
                                         uint32_t b0, uint32_t b1) {
    asm volatile("mma.sync.aligned.m16n8k16.row.col.f32.bf16.bf16.f32 "
                 "{%0,%1,%2,%3}, {%4,%5,%6,%7}, {%8,%9}, {%0,%1,%2,%3};"
                 : "+f"(d[0]), "+f"(d[1]), "+f"(d[2]), "+f"(d[3])
                 : "r"(a[0]), "r"(a[1]), "r"(a[2]), "r"(a[3]), "r"(b0), "r"(b1));
}

// SW128-style swizzle on [rows x 128 bytes] tiles
#define SWZ(x) ((x) ^ (((x) >> 3) & 0x70))

enum { EPI_Q = 0, EPI_K = 1, EPI_V = 2, EPI_SC = 3, EPI_AV = 4, EPI_OUT = 5 };

__device__ __forceinline__ void split_pair(float v0, float v1,
                                           __nv_bfloat162& h2, __nv_bfloat162& l2) {
    bf16 h0 = __float2bfloat16(v0), h1 = __float2bfloat16(v1);
    h2 = __halves2bfloat162(h0, h1);
    l2 = __halves2bfloat162(__float2bfloat16(v0 - __bfloat162float(h0)),
                            __float2bfloat16(v1 - __bfloat162float(h1)));
}

// ---- GEMM: C[128 x BN tile] = (Ah+Al)·(Bh+Bl)^T via 3-pass bf16 mma.sync ----
// A: [Mrows x K] k-major (ldA), B: [Nrows x K] k-major (ldB). K multiple of 64.
template<int EPI, int BN>
__global__ __launch_bounds__(256, 1)
void tc_gemm(const bf16* __restrict__ Ah, const bf16* __restrict__ Al,
             const bf16* __restrict__ Bh, const bf16* __restrict__ Bl,
             float* __restrict__ Cf, bf16* __restrict__ Ch, bf16* __restrict__ Cl,
             int Kdim, int ldA, int ldB, long long sA, long long sB, float scale)
{
    constexpr int TILE_A  = 128 * 128;      // 128x64 bf16 bytes
    constexpr int TILE_Bb = BN * 128;       // BN x64 bf16 bytes
    constexpr int BUF     = 2 * TILE_A + 2 * TILE_Bb;
    constexpr int NBp     = BN / 32;        // B 16B-pieces per thread per tile
    constexpr int WN      = BN / 4;         // warp n-width (warps 2x4)
    constexpr int NT      = WN / 8;
    constexpr int NTP     = WN / 16;

    extern __shared__ char smem[];
    const int bx = blockIdx.x, by = blockIdx.y, bz = blockIdx.z;
    if (EPI == EPI_SC && bx > by) return;   // causal block skip

    const int tid = threadIdx.x, wid = tid >> 5, lane = tid & 31;
    const int wm = wid >> 2, wn = wid & 3;  // 2x4 warp grid
    const int m0 = by * 128, n0 = bx * BN;

    Ah += (size_t)bz * sA;  Al += (size_t)bz * sA;
    Bh += (size_t)bz * sB;  Bl += (size_t)bz * sB;

    int kend = Kdim;
    if (EPI == EPI_AV) kend = (Kdim < m0 + 128) ? Kdim : (m0 + 128);
    const int NC = kend >> 6;

    const uint32_t sb = (smem_u32(smem) + 1023) & ~1023u;

    // staging coords (16B pieces): A has 4/thread, B has NBp/thread
    int arow[4], acol[4]; uint32_t aoff[4];
    #pragma unroll
    for (int t = 0; t < 4; t++) {
        int i = tid + t * 256;
        arow[t] = i >> 3; acol[t] = (i & 7) * 8;
        aoff[t] = SWZ((uint32_t)(arow[t] * 128 + acol[t] * 2));
    }
    int brow[NBp], bcol[NBp]; uint32_t boff[NBp];
    #pragma unroll
    for (int t = 0; t < NBp; t++) {
        int i = tid + t * 256;
        brow[t] = i >> 3; bcol[t] = (i & 7) * 8;
        boff[t] = SWZ((uint32_t)(brow[t] * 128 + bcol[t] * 2));
    }
    auto CPAC = [&](int c, int buf) {
        const int k0 = c * 64;
        const uint32_t b0 = sb + buf * BUF;
        #pragma unroll
        for (int t = 0; t < 4; t++) {
            const size_t ao = (size_t)(m0 + arow[t]) * ldA + k0 + acol[t];
            cpa16(b0          + aoff[t], Ah + ao);
            cpa16(b0 + TILE_A + aoff[t], Al + ao);
        }
        #pragma unroll
        for (int t = 0; t < NBp; t++) {
            const size_t bo = (size_t)(n0 + brow[t]) * ldB + k0 + bcol[t];
            cpa16(b0 + 2*TILE_A           + boff[t], Bh + bo);
            cpa16(b0 + 2*TILE_A + TILE_Bb + boff[t], Bl + bo);
        }
    };

    // ldmatrix lane address components
    const int aRow  = lane & 15;
    const uint32_t aHi  = ((lane >> 4) & 1) * 16;
    const uint32_t aXor = (uint32_t)((aRow & 7) << 4);
    uint32_t aRowOff[4];
    #pragma unroll
    for (int mt = 0; mt < 4; mt++)
        aRowOff[mt] = (uint32_t)((wm * 64 + mt * 16 + aRow) * 128);

    const int bN    = (lane & 7) + ((lane >> 4) & 1) * 8;
    const uint32_t bHi  = ((lane >> 3) & 1) * 16;
    const uint32_t bXor = (uint32_t)((bN & 7) << 4);
    uint32_t bRowOff[NTP];
    #pragma unroll
    for (int ntp = 0; ntp < NTP; ntp++)
        bRowOff[ntp] = (uint32_t)((wn * WN + ntp * 16 + bN) * 128);

    float acc[4][NT][4];
    #pragma unroll
    for (int i = 0; i < 4; i++)
        #pragma unroll
        for (int j = 0; j < NT; j++)
            #pragma unroll
            for (int q = 0; q < 4; q++) acc[i][j][q] = 0.0f;

    CPAC(0, 0); CP_COMMIT();

    for (int c = 0; c < NC; c++) {
        const int buf = c & 1;
        if (c + 1 < NC) { CPAC(c + 1, buf ^ 1); CP_COMMIT(); CP_WAIT1(); }
        else            { CP_WAIT0(); }
        __syncthreads();

        const uint32_t tAh = sb + buf * BUF;
        const uint32_t tAl = tAh + TILE_A;
        const uint32_t tBh = tAh + 2 * TILE_A;
        const uint32_t tBl = tBh + TILE_Bb;

        #pragma unroll
        for (int kb = 0; kb < 4; kb++) {
            const uint32_t akc = (uint32_t)(kb * 32) + aHi;
            const uint32_t bkc = (uint32_t)(kb * 32) + bHi;

            uint32_t ah[4][4], al[4][4];
            #pragma unroll
            for (int mt = 0; mt < 4; mt++) {
                const uint32_t off = aRowOff[mt] + (akc ^ aXor);
                ldsm_x4(ah[mt], tAh + off);
                ldsm_x4(al[mt], tAl + off);
            }
            #pragma unroll
            for (int ntp = 0; ntp < NTP; ntp++) {
                uint32_t bh[4], bl[4];
                const uint32_t off = bRowOff[ntp] + (bkc ^ bXor);
                ldsm_x4(bh, tBh + off);
                ldsm_x4(bl, tBl + off);
                #pragma unroll
                for (int mt = 0; mt < 4; mt++) {
                    mma16816(acc[mt][2*ntp],   ah[mt], bh[0], bh[1]);
                    mma16816(acc[mt][2*ntp],   ah[mt], bl[0], bl[1]);
                    mma16816(acc[mt][2*ntp],   al[mt], bh[0], bh[1]);
                    mma16816(acc[mt][2*ntp+1], ah[mt], bh[2], bh[3]);
                    mma16816(acc[mt][2*ntp+1], ah[mt], bl[2], bl[3]);
                    mma16816(acc[mt][2*ntp+1], al[mt], bh[2], bh[3]);
                }
            }
        }
        __syncthreads();
    }

    // ---------------- epilogue (register fragments) ----------------
    const int r0 = lane >> 2;
    const int cp2 = (lane & 3) * 2;

    #pragma unroll
    for (int mt = 0; mt < 4; mt++) {
        #pragma unroll
        for (int nt = 0; nt < NT; nt++) {
            const float* cc = acc[mt][nt];
            const int gmA = m0 + wm * 64 + mt * 16 + r0;
            const int gmB = gmA + 8;
            const int nl  = wn * WN + nt * 8 + cp2;
            const int gn  = n0 + nl;

            if (EPI == EPI_SC) {
                float* dst = Cf + (size_t)bz * Sd * Sd;
                *reinterpret_cast<float2*>(dst + (size_t)gmA * Sd + gn) =
                    make_float2(cc[0] * scale, cc[1] * scale);
                *reinterpret_cast<float2*>(dst + (size_t)gmB * Sd + gn) =
                    make_float2(cc[2] * scale, cc[3] * scale);
            } else if (EPI == EPI_OUT) {
                *reinterpret_cast<float2*>(Cf + (size_t)gmA * Dd + gn) = make_float2(cc[0], cc[1]);
                *reinterpret_cast<float2*>(Cf + (size_t)gmB * Dd + gn) = make_float2(cc[2], cc[3]);
            } else if (EPI == EPI_AV) {
                const int b = bz >> 4, h = bz & 15;
                __nv_bfloat162 h2, l2;
                size_t baseA = ((size_t)(b * Sd + gmA)) * Dd + h * HDd + nl;
                size_t baseB = ((size_t)(b * Sd + gmB)) * Dd + h * HDd + nl;
                split_pair(cc[0], cc[1], h2, l2);
                *reinterpret_cast<__nv_bfloat162*>(Ch + baseA) = h2;
                *reinterpret_cast<__nv_bfloat162*>(Cl + baseA) = l2;
                split_pair(cc[2], cc[3], h2, l2);
                *reinterpret_cast<__nv_bfloat162*>(Ch + baseB) = h2;
                *reinterpret_cast<__nv_bfloat162*>(Cl + baseB) = l2;
            } else {
                // projections: head index from global n (BN tile may span 2 heads)
                const int h  = gn >> 7;
                const int hd = gn & (HDd - 1);
                #pragma unroll
                for (int half = 0; half < 2; half++) {
                    const int gm = half ? gmB : gmA;
                    const float v0 = cc[half * 2], v1 = cc[half * 2 + 1];
                    const int b = gm >> 11, s = gm & (Sd - 1);
                    const size_t base = (((size_t)(b * Hd + h)) * Sd + s) * HDd + hd;
                    if (EPI == EPI_K || EPI == EPI_V)
                        *reinterpret_cast<float2*>(Cf + base) = make_float2(v0, v1);
                    if (EPI == EPI_V) {
                        const size_t ti = (((size_t)(b * Hd + h)) * HDd + hd) * Sd + s;
                        bf16 h0 = __float2bfloat16(v0), h1 = __float2bfloat16(v1);
                        Ch[ti]      = h0;
                        Ch[ti + Sd] = h1;
                        Cl[ti]      = __float2bfloat16(v0 - __bfloat162float(h0));
                        Cl[ti + Sd] = __float2bfloat16(v1 - __bfloat162float(h1));
                    } else {
                        __nv_bfloat162 h2, l2;
                        split_pair(v0, v1, h2, l2);
                        *reinterpret_cast<__nv_bfloat162*>(Ch + base) = h2;
                        *reinterpret_cast<__nv_bfloat162*>(Cl + base) = l2;
                    }
                }
            }
        }
    }
}

// ---------------- causal softmax: fp32 scores -> bf16 hi/lo probs ----------------
__global__ void softmax_kernel(const float* __restrict__ S,
                               bf16* __restrict__ Ph, bf16* __restrict__ Pl)
{
    const int row = blockIdx.x, bh = blockIdx.y, tid = threadIdx.x;
    const float* p = S + (size_t)bh * Sd * Sd + (size_t)row * Sd;
    bf16* ph = Ph + (size_t)bh * Sd * Sd + (size_t)row * Sd;
    bf16* pl = Pl + (size_t)bh * Sd * Sd + (size_t)row * Sd;
    const int n = row + 1;
    const int kmax = ((row >> 7) + 1) << 7;

    __shared__ float red[256];
    float v[8]; int cnt = 0; float mx = -FLT_MAX;
    for (int j = tid; j < n; j += 256) { float x = p[j]; v[cnt++] = x; mx = fmaxf(mx, x); }
    red[tid] = mx; __syncthreads();
    #pragma unroll
    for (int s2 = 128; s2 > 0; s2 >>= 1) { if (tid < s2) red[tid] = fmaxf(red[tid], red[tid + s2]); __syncthreads(); }
    mx = red[0]; __syncthreads();

    float sum = 0.0f;
    for (int c = 0; c < cnt; c++) { v[c] = expf(v[c] - mx); sum += v[c]; }
    red[tid] = sum; __syncthreads();
    #pragma unroll
    for (int s2 = 128; s2 > 0; s2 >>= 1) { if (tid < s2) red[tid] += red[tid + s2]; __syncthreads(); }
    const float inv = 1.0f / red[0];

    cnt = 0;
    for (int j = tid; j < kmax; j += 256) {
        float val = (j < n) ? v[cnt++] * inv : 0.0f;
        bf16 hh = __float2bfloat16(val);
        ph[j] = hh;
        pl[j] = __float2bfloat16(val - __bfloat162float(hh));
    }
}

// ---------------- fp32 -> (bf16 hi, bf16 lo) split ----------------
__global__ void split_kernel(const float4* __restrict__ in,
                             __nv_bfloat162* __restrict__ hi, __nv_bfloat162* __restrict__ lo,
                             int n4)
{
    int i = blockIdx.x * 256 + threadIdx.x;
    if (i >= n4) return;
    float4 x = in[i];
    __nv_bfloat162 h2, l2;
    split_pair(x.x, x.y, h2, l2); hi[2*i]   = h2; lo[2*i]   = l2;
    split_pair(x.z, x.w, h2, l2); hi[2*i+1] = h2; lo[2*i+1] = l2;
}

#define GSMEM_OF(BN) (1024 + 2 * (2 * 128 * 128 + 2 * (BN) * 128))

extern "C" void kernel_launch(void* const* d_in, const int* in_sizes, int n_in,
                              void* d_out, int out_size)
{
    const float* x  = (const float*)d_in[0];
    const float* Wq = (const float*)d_in[1];
    const float* Wk = (const float*)d_in[2];
    const float* Wv = (const float*)d_in[3];
    const float* Wo = (const float*)d_in[4];

    float* out  = (float*)d_out;
    float* kout = out  + (size_t)Md * Dd;
    float* vout = kout + (size_t)Md * Dd;

    bf16 *xh,*xl,*wqh,*wql,*wkh,*wkl,*wvh,*wvl,*woh,*wol;
    bf16 *qh,*ql,*kh,*kl,*vth,*vtl,*pph,*ppl,*omh,*oml;
    float* sp;
    cudaGetSymbolAddress((void**)&xh, g_xh);   cudaGetSymbolAddress((void**)&xl, g_xl);
    cudaGetSymbolAddress((void**)&wqh, g_wqh); cudaGetSymbolAddress((void**)&wql, g_wql);
    cudaGetSymbolAddress((void**)&wkh, g_wkh); cudaGetSymbolAddress((void**)&wkl, g_wkl);
    cudaGetSymbolAddress((void**)&wvh, g_wvh); cudaGetSymbolAddress((void**)&wvl, g_wvl);
    cudaGetSymbolAddress((void**)&woh, g_woh); cudaGetSymbolAddress((void**)&wol, g_wol);
    cudaGetSymbolAddress((void**)&qh, g_qh);   cudaGetSymbolAddress((void**)&ql, g_ql);
    cudaGetSymbolAddress((void**)&kh, g_kh);   cudaGetSymbolAddress((void**)&kl, g_kl);
    cudaGetSymbolAddress((void**)&vth, g_vth); cudaGetSymbolAddress((void**)&vtl, g_vtl);
    cudaGetSymbolAddress((void**)&pph, g_ph);  cudaGetSymbolAddress((void**)&ppl, g_pl);
    cudaGetSymbolAddress((void**)&omh, g_omh); cudaGetSymbolAddress((void**)&oml, g_oml);
    cudaGetSymbolAddress((void**)&sp, g_s);

    cudaFuncSetAttribute(tc_gemm<EPI_Q,  256>, cudaFuncAttributeMaxDynamicSharedMemorySize, GSMEM_OF(256));
    cudaFuncSetAttribute(tc_gemm<EPI_K,  256>, cudaFuncAttributeMaxDynamicSharedMemorySize, GSMEM_OF(256));
    cudaFuncSetAttribute(tc_gemm<EPI_V,  256>, cudaFuncAttributeMaxDynamicSharedMemorySize, GSMEM_OF(256));
    cudaFuncSetAttribute(tc_gemm<EPI_OUT,256>, cudaFuncAttributeMaxDynamicSharedMemorySize, GSMEM_OF(256));
    cudaFuncSetAttribute(tc_gemm<EPI_SC, 128>, cudaFuncAttributeMaxDynamicSharedMemorySize, GSMEM_OF(128));
    cudaFuncSetAttribute(tc_gemm<EPI_AV, 128>, cudaFuncAttributeMaxDynamicSharedMemorySize, GSMEM_OF(128));

    // 0) split inputs into bf16 hi/lo
    split_kernel<<<(Md*Dd/4 + 255)/256, 256>>>((const float4*)x,  (__nv_bfloat162*)xh,  (__nv_bfloat162*)xl,  Md*Dd/4);
    split_kernel<<<(Dd*Dd/4 + 255)/256, 256>>>((const float4*)Wq, (__nv_bfloat162*)wqh, (__nv_bfloat162*)wql, Dd*Dd/4);
    split_kernel<<<(Dd*Dd/4 + 255)/256, 256>>>((const float4*)Wk, (__nv_bfloat162*)wkh, (__nv_bfloat162*)wkl, Dd*Dd/4);
    split_kernel<<<(Dd*Dd/4 + 255)/256, 256>>>((const float4*)Wv, (__nv_bfloat162*)wvh, (__nv_bfloat162*)wvl, Dd*Dd/4);
    split_kernel<<<(Dd*Dd/4 + 255)/256, 256>>>((const float4*)Wo, (__nv_bfloat162*)woh, (__nv_bfloat162*)wol, Dd*Dd/4);

    const float scale = 1.0f / sqrtf((float)HDd);
    dim3 blk(256);

    // 1) QKV projections (NT, BN=256): C = x · W^T, fused split-head + hi/lo epilogues
    dim3 gP(Dd/256, Md/128, 1);
    tc_gemm<EPI_Q,256><<<gP, blk, GSMEM_OF(256)>>>(xh, xl, wqh, wql, nullptr, qh, ql, Dd, Dd, Dd, 0, 0, 1.0f);
    tc_gemm<EPI_K,256><<<gP, blk, GSMEM_OF(256)>>>(xh, xl, wkh, wkl, kout,   kh, kl, Dd, Dd, Dd, 0, 0, 1.0f);
    tc_gemm<EPI_V,256><<<gP, blk, GSMEM_OF(256)>>>(xh, xl, wvh, wvl, vout,   vth, vtl, Dd, Dd, Dd, 0, 0, 1.0f);

    // 2) scores (NT, BN=128, causal block-skip): Q · K^T * scale
    dim3 gS(Sd/128, Sd/128, BHd);
    tc_gemm<EPI_SC,128><<<gS, blk, GSMEM_OF(128)>>>(qh, ql, kh, kl, sp, nullptr, nullptr,
                                                    HDd, HDd, HDd,
                                                    (long long)Sd*HDd, (long long)Sd*HDd, scale);

    // 3) softmax (fp32 in, bf16 hi/lo out, zeros to block boundary)
    softmax_kernel<<<dim3(Sd, BHd), 256>>>(sp, pph, ppl);

    // 4) P · V (k-clamped per row tile), via V^T so B is k-major
    dim3 gAV(1, Sd/128, BHd);
    tc_gemm<EPI_AV,128><<<gAV, blk, GSMEM_OF(128)>>>(pph, ppl, vth, vtl, nullptr, omh, oml,
                                                     Sd, Sd, Sd,
                                                     (long long)Sd*Sd, (long long)HDd*Sd, 1.0f);

    // 5) output projection (NT, BN=256) -> fp32 out
    dim3 gO(Dd/256, Md/128, 1);
    tc_gemm<EPI_OUT,256><<<gO, blk, GSMEM_OF(256)>>>(omh, oml, woh, wol, out, nullptr, nullptr,
                                                     Dd, Dd, Dd, 0, 0, 1.0f);
}

// round 7
// speedup vs baseline: 3.5732x; 1.2263x over previous
#include <cuda_runtime.h>
#include <cuda_fp16.h>
#include <math.h>
#include <float.h>
#include <stdint.h>

#define Bd  2
#define Sd  2048
#define Dd  2048
#define Hd  16
#define HDd 128
#define Md  (Bd*Sd)
#define BHd (Bd*Hd)

typedef __half fp16;

// ---------------- scratch (__device__ globals; allocation-free rule) ----------------
__device__ fp16 g_xh[(size_t)Md*Dd],  g_xl[(size_t)Md*Dd];
__device__ fp16 g_wqh[(size_t)Dd*Dd];                       // weights: hi only (2-pass)
__device__ fp16 g_wkh[(size_t)Dd*Dd];
__device__ fp16 g_wvh[(size_t)Dd*Dd];
__device__ fp16 g_woh[(size_t)Dd*Dd];
__device__ fp16 g_qh[(size_t)BHd*Sd*HDd], g_ql[(size_t)BHd*Sd*HDd];
__device__ fp16 g_kh[(size_t)BHd*Sd*HDd], g_kl[(size_t)BHd*Sd*HDd];
__device__ fp16 g_vth[(size_t)BHd*HDd*Sd], g_vtl[(size_t)BHd*HDd*Sd]; // V^T: [HD][S]
__device__ float g_s[(size_t)BHd*Sd*Sd];                               // fp32 scores
__device__ fp16 g_ph[(size_t)BHd*Sd*Sd], g_pl[(size_t)BHd*Sd*Sd];     // probs hi/lo
__device__ fp16 g_omh[(size_t)Md*Dd], g_oml[(size_t)Md*Dd];           // attn out hi/lo

// ---------------- PTX helpers (sm_80-class only) ----------------
__device__ __forceinline__ uint32_t smem_u32(const void* p) {
    uint32_t a;
    asm("{ .reg .u64 t; cvta.to.shared.u64 t, %1; cvt.u32.u64 %0, t; }" : "=r"(a) : "l"(p));
    return a;
}
__device__ __forceinline__ void cpa16(uint32_t dst, const void* src) {
    asm volatile("cp.async.cg.shared.global [%0], [%1], 16;" :: "r"(dst), "l"(src) : "memory");
}
#define CP_COMMIT() asm volatile("cp.async.commit_group;" ::: "memory")
#define CP_WAIT0()  asm volatile("cp.async.wait_group 0;" ::: "memory")
#define CP_WAIT1()  asm volatile("cp.async.wait_group 1;" ::: "memory")

__device__ __forceinline__ void ldsm_x4(uint32_t (&r)[4], uint32_t addr) {
    asm volatile("ldmatrix.sync.aligned.m8n8.x4.shared.b16 {%0,%1,%2,%3}, [%4];"
                 : "=r"(r[0]), "=r"(r[1]), "=r"(r[2]), "=r"(r[3]) : "r"(addr));
}
__device__ __forceinline__ void mma16816(float (&d)[4], const uint32_t (&a)[4],
                                         uint32_t b0, uint32_t b1) {
    asm volatile("mma.sync.aligned.m16n8k16.row.col.f32.f16.f16.f32 "
                 "{%0,%1,%2,%3}, {%4,%5,%6,%7}, {%8,%9}, {%0,%1,%2,%3};"
                 : "+f"(d[0]), "+f"(d[1]), "+f"(d[2]), "+f"(d[3])
                 : "r"(a[0]), "r"(a[1]), "r"(a[2]), "r"(a[3]), "r"(b0), "r"(b1));
}

// SW128-style swizzle on [rows x 128 bytes] tiles
#define SWZ(x) ((x) ^ (((x) >> 3) & 0x70))

enum { EPI_Q = 0, EPI_K = 1, EPI_V = 2, EPI_SC = 3, EPI_AV = 4, EPI_OUT = 5 };

__device__ __forceinline__ void split_pair(float v0, float v1, __half2& h2, __half2& l2) {
    fp16 h0 = __float2half(v0), h1 = __float2half(v1);
    h2 = __halves2half2(h0, h1);
    l2 = __halves2half2(__float2half(v0 - __half2float(h0)),
                        __float2half(v1 - __half2float(h1)));
}

// ---- GEMM: C[128 x BN tile] = A·B^T via PASSES-pass fp16 mma.sync ----
// PASSES==3: Ah·Bh + Ah·Bl + Al·Bh.  PASSES==2: Ah·Bh + Al·Bh (B-lo never staged).
// A: [Mrows x K] k-major (ldA), B: [Nrows x K] k-major (ldB). K multiple of 64.
template<int EPI, int BN, int PASSES>
__global__ __launch_bounds__(256, 1)
void tc_gemm(const fp16* __restrict__ Ah, const fp16* __restrict__ Al,
             const fp16* __restrict__ Bh, const fp16* __restrict__ Bl,
             float* __restrict__ Cf, fp16* __restrict__ Ch, fp16* __restrict__ Cl,
             int Kdim, int ldA, int ldB, long long sA, long long sB, float scale)
{
    constexpr int TILE_A  = 128 * 128;      // 128x64 fp16 bytes
    constexpr int TILE_Bb = BN * 128;
    constexpr int NBT     = (PASSES == 3) ? 2 : 1;
    constexpr int BUF     = 2 * TILE_A + NBT * TILE_Bb;
    constexpr int NBp     = BN / 32;
    constexpr int WN      = BN / 4;
    constexpr int NT      = WN / 8;
    constexpr int NTP     = WN / 16;

    extern __shared__ char smem[];
    const int bx = blockIdx.x, by = blockIdx.y, bz = blockIdx.z;
    if (EPI == EPI_SC && bx > by) return;   // causal block skip

    const int tid = threadIdx.x, wid = tid >> 5, lane = tid & 31;
    const int wm = wid >> 2, wn = wid & 3;
    const int m0 = by * 128, n0 = bx * BN;

    Ah += (size_t)bz * sA;  Al += (size_t)bz * sA;
    Bh += (size_t)bz * sB;
    if (PASSES == 3) Bl += (size_t)bz * sB;

    int kend = Kdim;
    if (EPI == EPI_AV) kend = (Kdim < m0 + 128) ? Kdim : (m0 + 128);
    const int NC = kend >> 6;

    const uint32_t sb = (smem_u32(smem) + 1023) & ~1023u;

    int arow[4], acol[4]; uint32_t aoff[4];
    #pragma unroll
    for (int t = 0; t < 4; t++) {
        int i = tid + t * 256;
        arow[t] = i >> 3; acol[t] = (i & 7) * 8;
        aoff[t] = SWZ((uint32_t)(arow[t] * 128 + acol[t] * 2));
    }
    int brow[NBp], bcol[NBp]; uint32_t boff[NBp];
    #pragma unroll
    for (int t = 0; t < NBp; t++) {
        int i = tid + t * 256;
        brow[t] = i >> 3; bcol[t] = (i & 7) * 8;
        boff[t] = SWZ((uint32_t)(brow[t] * 128 + bcol[t] * 2));
    }
    auto CPAC = [&](int c, int buf) {
        const int k0 = c * 64;
        const uint32_t b0 = sb + buf * BUF;
        #pragma unroll
        for (int t = 0; t < 4; t++) {
            const size_t ao = (size_t)(m0 + arow[t]) * ldA + k0 + acol[t];
            cpa16(b0          + aoff[t], Ah + ao);
            cpa16(b0 + TILE_A + aoff[t], Al + ao);
        }
        #pragma unroll
        for (int t = 0; t < NBp; t++) {
            const size_t bo = (size_t)(n0 + brow[t]) * ldB + k0 + bcol[t];
            cpa16(b0 + 2*TILE_A + boff[t], Bh + bo);
            if (PASSES == 3)
                cpa16(b0 + 2*TILE_A + TILE_Bb + boff[t], Bl + bo);
        }
    };

    const int aRow  = lane & 15;
    const uint32_t aHi  = ((lane >> 4) & 1) * 16;
    const uint32_t aXor = (uint32_t)((aRow & 7) << 4);
    uint32_t aRowOff[4];
    #pragma unroll
    for (int mt = 0; mt < 4; mt++)
        aRowOff[mt] = (uint32_t)((wm * 64 + mt * 16 + aRow) * 128);

    const int bN    = (lane & 7) + ((lane >> 4) & 1) * 8;
    const uint32_t bHi  = ((lane >> 3) & 1) * 16;
    const uint32_t bXor = (uint32_t)((bN & 7) << 4);
    uint32_t bRowOff[NTP];
    #pragma unroll
    for (int ntp = 0; ntp < NTP; ntp++)
        bRowOff[ntp] = (uint32_t)((wn * WN + ntp * 16 + bN) * 128);

    float acc[4][NT][4];
    #pragma unroll
    for (int i = 0; i < 4; i++)
        #pragma unroll
        for (int j = 0; j < NT; j++)
            #pragma unroll
            for (int q = 0; q < 4; q++) acc[i][j][q] = 0.0f;

    CPAC(0, 0); CP_COMMIT();

    for (int c = 0; c < NC; c++) {
        const int buf = c & 1;
        if (c + 1 < NC) { CPAC(c + 1, buf ^ 1); CP_COMMIT(); CP_WAIT1(); }
        else            { CP_WAIT0(); }
        __syncthreads();

        const uint32_t tAh = sb + buf * BUF;
        const uint32_t tAl = tAh + TILE_A;
        const uint32_t tBh = tAh + 2 * TILE_A;
        const uint32_t tBl = tBh + TILE_Bb;

        #pragma unroll
        for (int kb = 0; kb < 4; kb++) {
            const uint32_t akc = (uint32_t)(kb * 32) + aHi;
            const uint32_t bkc = (uint32_t)(kb * 32) + bHi;

            uint32_t ah[4][4], al[4][4];
            #pragma unroll
            for (int mt = 0; mt < 4; mt++) {
                const uint32_t off = aRowOff[mt] + (akc ^ aXor);
                ldsm_x4(ah[mt], tAh + off);
                ldsm_x4(al[mt], tAl + off);
            }
            #pragma unroll
            for (int ntp = 0; ntp < NTP; ntp++) {
                uint32_t bh[4], bl[4];
                const uint32_t off = bRowOff[ntp] + (bkc ^ bXor);
                ldsm_x4(bh, tBh + off);
                if (PASSES == 3) ldsm_x4(bl, tBl + off);
                #pragma unroll
                for (int mt = 0; mt < 4; mt++) {
                    mma16816(acc[mt][2*ntp],   ah[mt], bh[0], bh[1]);
                    if (PASSES == 3) mma16816(acc[mt][2*ntp], ah[mt], bl[0], bl[1]);
                    mma16816(acc[mt][2*ntp],   al[mt], bh[0], bh[1]);
                    mma16816(acc[mt][2*ntp+1], ah[mt], bh[2], bh[3]);
                    if (PASSES == 3) mma16816(acc[mt][2*ntp+1], ah[mt], bl[2], bl[3]);
                    mma16816(acc[mt][2*ntp+1], al[mt], bh[2], bh[3]);
                }
            }
        }
        __syncthreads();
    }

    // ---------------- epilogue (register fragments) ----------------
    const int r0 = lane >> 2;
    const int cp2 = (lane & 3) * 2;

    #pragma unroll
    for (int mt = 0; mt < 4; mt++) {
        #pragma unroll
        for (int nt = 0; nt < NT; nt++) {
            const float* cc = acc[mt][nt];
            const int gmA = m0 + wm * 64 + mt * 16 + r0;
            const int gmB = gmA + 8;
            const int nl  = wn * WN + nt * 8 + cp2;
            const int gn  = n0 + nl;

            if (EPI == EPI_SC) {
                float* dst = Cf + (size_t)bz * Sd * Sd;
                *reinterpret_cast<float2*>(dst + (size_t)gmA * Sd + gn) =
                    make_float2(cc[0] * scale, cc[1] * scale);
                *reinterpret_cast<float2*>(dst + (size_t)gmB * Sd + gn) =
                    make_float2(cc[2] * scale, cc[3] * scale);
            } else if (EPI == EPI_OUT) {
                *reinterpret_cast<float2*>(Cf + (size_t)gmA * Dd + gn) = make_float2(cc[0], cc[1]);
                *reinterpret_cast<float2*>(Cf + (size_t)gmB * Dd + gn) = make_float2(cc[2], cc[3]);
            } else if (EPI == EPI_AV) {
                const int b = bz >> 4, h = bz & 15;
                __half2 h2, l2;
                size_t baseA = ((size_t)(b * Sd + gmA)) * Dd + h * HDd + nl;
                size_t baseB = ((size_t)(b * Sd + gmB)) * Dd + h * HDd + nl;
                split_pair(cc[0], cc[1], h2, l2);
                *reinterpret_cast<__half2*>(Ch + baseA) = h2;
                *reinterpret_cast<__half2*>(Cl + baseA) = l2;
                split_pair(cc[2], cc[3], h2, l2);
                *reinterpret_cast<__half2*>(Ch + baseB) = h2;
                *reinterpret_cast<__half2*>(Cl + baseB) = l2;
            } else {
                const int h  = gn >> 7;
                const int hd = gn & (HDd - 1);
                #pragma unroll
                for (int half = 0; half < 2; half++) {
                    const int gm = half ? gmB : gmA;
                    const float v0 = cc[half * 2], v1 = cc[half * 2 + 1];
                    const int b = gm >> 11, s = gm & (Sd - 1);
                    const size_t base = (((size_t)(b * Hd + h)) * Sd + s) * HDd + hd;
                    if (EPI == EPI_K || EPI == EPI_V)
                        *reinterpret_cast<float2*>(Cf + base) = make_float2(v0, v1);
                    if (EPI == EPI_V) {
                        const size_t ti = (((size_t)(b * Hd + h)) * HDd + hd) * Sd + s;
                        fp16 h0 = __float2half(v0), h1 = __float2half(v1);
                        Ch[ti]      = h0;
                        Ch[ti + Sd] = h1;
                        Cl[ti]      = __float2half(v0 - __half2float(h0));
                        Cl[ti + Sd] = __float2half(v1 - __half2float(h1));
                    } else {
                        __half2 h2, l2;
                        split_pair(v0, v1, h2, l2);
                        *reinterpret_cast<__half2*>(Ch + base) = h2;
                        *reinterpret_cast<__half2*>(Cl + base) = l2;
                    }
                }
            }
        }
    }
}

// ---------------- causal softmax: fp32 scores -> fp16 hi/lo probs ----------------
__global__ void softmax_kernel(const float* __restrict__ S,
                               fp16* __restrict__ Ph, fp16* __restrict__ Pl)
{
    const int row = blockIdx.x, bh = blockIdx.y, tid = threadIdx.x;
    const float* p = S + (size_t)bh * Sd * Sd + (size_t)row * Sd;
    fp16* ph = Ph + (size_t)bh * Sd * Sd + (size_t)row * Sd;
    fp16* pl = Pl + (size_t)bh * Sd * Sd + (size_t)row * Sd;
    const int n = row + 1;
    const int kmax = ((row >> 7) + 1) << 7;   // zero out to 128-block boundary (AV clamp)

    __shared__ float red[256];
    float v[8]; int cnt = 0; float mx = -FLT_MAX;
    for (int j = tid; j < n; j += 256) { float x = p[j]; v[cnt++] = x; mx = fmaxf(mx, x); }
    red[tid] = mx; __syncthreads();
    #pragma unroll
    for (int s2 = 128; s2 > 0; s2 >>= 1) { if (tid < s2) red[tid] = fmaxf(red[tid], red[tid + s2]); __syncthreads(); }
    mx = red[0]; __syncthreads();

    float sum = 0.0f;
    for (int c = 0; c < cnt; c++) { v[c] = expf(v[c] - mx); sum += v[c]; }
    red[tid] = sum; __syncthreads();
    #pragma unroll
    for (int s2 = 128; s2 > 0; s2 >>= 1) { if (tid < s2) red[tid] += red[tid + s2]; __syncthreads(); }
    const float inv = 1.0f / red[0];

    cnt = 0;
    for (int j = tid; j < kmax; j += 256) {
        float val = (j < n) ? v[cnt++] * inv : 0.0f;
        fp16 hh = __float2half(val);
        ph[j] = hh;
        pl[j] = __float2half(val - __half2float(hh));
    }
}

// ---------------- fp32 -> (fp16 hi, fp16 lo) split ----------------
__global__ void split_kernel(const float4* __restrict__ in,
                             __half2* __restrict__ hi, __half2* __restrict__ lo, int n4)
{
    int i = blockIdx.x * 256 + threadIdx.x;
    if (i >= n4) return;
    float4 x = in[i];
    __half2 h2, l2;
    split_pair(x.x, x.y, h2, l2); hi[2*i]   = h2; lo[2*i]   = l2;
    split_pair(x.z, x.w, h2, l2); hi[2*i+1] = h2; lo[2*i+1] = l2;
}

// ---------------- fp32 -> fp16 hi only (weights, 2-pass GEMMs) ----------------
__global__ void split_hi_kernel(const float4* __restrict__ in, __half2* __restrict__ hi, int n4)
{
    int i = blockIdx.x * 256 + threadIdx.x;
    if (i >= n4) return;
    float4 x = in[i];
    hi[2*i]   = __halves2half2(__float2half(x.x), __float2half(x.y));
    hi[2*i+1] = __halves2half2(__float2half(x.z), __float2half(x.w));
}

#define GSMEM_OF(BN, P) (1024 + 2 * (2 * 128 * 128 + (((P) == 3) ? 2 : 1) * (BN) * 128))

extern "C" void kernel_launch(void* const* d_in, const int* in_sizes, int n_in,
                              void* d_out, int out_size)
{
    const float* x  = (const float*)d_in[0];
    const float* Wq = (const float*)d_in[1];
    const float* Wk = (const float*)d_in[2];
    const float* Wv = (const float*)d_in[3];
    const float* Wo = (const float*)d_in[4];

    float* out  = (float*)d_out;
    float* kout = out  + (size_t)Md * Dd;
    float* vout = kout + (size_t)Md * Dd;

    fp16 *xh,*xl,*wqh,*wkh,*wvh,*woh;
    fp16 *qh,*ql,*kh,*kl,*vth,*vtl,*pph,*ppl,*omh,*oml;
    float* sp;
    cudaGetSymbolAddress((void**)&xh, g_xh);   cudaGetSymbolAddress((void**)&xl, g_xl);
    cudaGetSymbolAddress((void**)&wqh, g_wqh); cudaGetSymbolAddress((void**)&wkh, g_wkh);
    cudaGetSymbolAddress((void**)&wvh, g_wvh); cudaGetSymbolAddress((void**)&woh, g_woh);
    cudaGetSymbolAddress((void**)&qh, g_qh);   cudaGetSymbolAddress((void**)&ql, g_ql);
    cudaGetSymbolAddress((void**)&kh, g_kh);   cudaGetSymbolAddress((void**)&kl, g_kl);
    cudaGetSymbolAddress((void**)&vth, g_vth); cudaGetSymbolAddress((void**)&vtl, g_vtl);
    cudaGetSymbolAddress((void**)&pph, g_ph);  cudaGetSymbolAddress((void**)&ppl, g_pl);
    cudaGetSymbolAddress((void**)&omh, g_omh); cudaGetSymbolAddress((void**)&oml, g_oml);
    cudaGetSymbolAddress((void**)&sp, g_s);

    cudaFuncSetAttribute(tc_gemm<EPI_Q,  256, 2>, cudaFuncAttributeMaxDynamicSharedMemorySize, GSMEM_OF(256, 2));
    cudaFuncSetAttribute(tc_gemm<EPI_K,  256, 2>, cudaFuncAttributeMaxDynamicSharedMemorySize, GSMEM_OF(256, 2));
    cudaFuncSetAttribute(tc_gemm<EPI_V,  256, 2>, cudaFuncAttributeMaxDynamicSharedMemorySize, GSMEM_OF(256, 2));
    cudaFuncSetAttribute(tc_gemm<EPI_OUT,256, 2>, cudaFuncAttributeMaxDynamicSharedMemorySize, GSMEM_OF(256, 2));
    cudaFuncSetAttribute(tc_gemm<EPI_SC, 128, 3>, cudaFuncAttributeMaxDynamicSharedMemorySize, GSMEM_OF(128, 3));
    cudaFuncSetAttribute(tc_gemm<EPI_AV, 128, 3>, cudaFuncAttributeMaxDynamicSharedMemorySize, GSMEM_OF(128, 3));

    // 0) split: x -> hi/lo; weights -> hi only (2-pass projections drop W-lo)
    split_kernel   <<<(Md*Dd/4 + 255)/256, 256>>>((const float4*)x,  (__half2*)xh, (__half2*)xl, Md*Dd/4);
    split_hi_kernel<<<(Dd*Dd/4 + 255)/256, 256>>>((const float4*)Wq, (__half2*)wqh, Dd*Dd/4);
    split_hi_kernel<<<(Dd*Dd/4 + 255)/256, 256>>>((const float4*)Wk, (__half2*)wkh, Dd*Dd/4);
    split_hi_kernel<<<(Dd*Dd/4 + 255)/256, 256>>>((const float4*)Wv, (__half2*)wvh, Dd*Dd/4);
    split_hi_kernel<<<(Dd*Dd/4 + 255)/256, 256>>>((const float4*)Wo, (__half2*)woh, Dd*Dd/4);

    const float scale = 1.0f / sqrtf((float)HDd);
    dim3 blk(256);

    // 1) QKV projections (NT, BN=256, 2-pass)
    dim3 gP(Dd/256, Md/128, 1);
    tc_gemm<EPI_Q,256,2><<<gP, blk, GSMEM_OF(256,2)>>>(xh, xl, wqh, nullptr, nullptr, qh, ql, Dd, Dd, Dd, 0, 0, 1.0f);
    tc_gemm<EPI_K,256,2><<<gP, blk, GSMEM_OF(256,2)>>>(xh, xl, wkh, nullptr, kout,   kh, kl, Dd, Dd, Dd, 0, 0, 1.0f);
    tc_gemm<EPI_V,256,2><<<gP, blk, GSMEM_OF(256,2)>>>(xh, xl, wvh, nullptr, vout,   vth, vtl, Dd, Dd, Dd, 0, 0, 1.0f);

    // 2) scores (NT, BN=128, 3-pass, causal block-skip): Q · K^T * scale
    dim3 gS(Sd/128, Sd/128, BHd);
    tc_gemm<EPI_SC,128,3><<<gS, blk, GSMEM_OF(128,3)>>>(qh, ql, kh, kl, sp, nullptr, nullptr,
                                                        HDd, HDd, HDd,
                                                        (long long)Sd*HDd, (long long)Sd*HDd, scale);

    // 3) softmax (fp32 in, fp16 hi/lo out, zeros to block boundary)
    softmax_kernel<<<dim3(Sd, BHd), 256>>>(sp, pph, ppl);

    // 4) P · V (3-pass, k-clamped per row tile), via V^T so B is k-major
    dim3 gAV(1, Sd/128, BHd);
    tc_gemm<EPI_AV,128,3><<<gAV, blk, GSMEM_OF(128,3)>>>(pph, ppl, vth, vtl, nullptr, omh, oml,
                                                         Sd, Sd, Sd,
                                                         (long long)Sd*Sd, (long long)HDd*Sd, 1.0f);

    // 5) output projection (NT, BN=256, 2-pass) -> fp32 out
    dim3 gO(Dd/256, Md/128, 1);
    tc_gemm<EPI_OUT,256,2><<<gO, blk, GSMEM_OF(256,2)>>>(omh, oml, woh, nullptr, out, nullptr, nullptr,
                                                         Dd, Dd, Dd, 0, 0, 1.0f);
}

// round 8
// speedup vs baseline: 3.6619x; 1.0248x over previous
#include <cuda_runtime.h>
#include <cuda_fp16.h>
#include <math.h>
#include <float.h>
#include <stdint.h>

#define Bd  2
#define Sd  2048
#define Dd  2048
#define Hd  16
#define HDd 128
#define Md  (Bd*Sd)
#define BHd (Bd*Hd)

typedef __half fp16;

// ---------------- scratch (__device__ globals; allocation-free rule) ----------------
__device__ fp16 g_xh[(size_t)Md*Dd],  g_xl[(size_t)Md*Dd];
__device__ fp16 g_wqh[(size_t)Dd*Dd], g_wkh[(size_t)Dd*Dd];
__device__ fp16 g_wvh[(size_t)Dd*Dd], g_woh[(size_t)Dd*Dd];
__device__ fp16 g_qh[(size_t)BHd*Sd*HDd], g_ql[(size_t)BHd*Sd*HDd];  // Q pre-scaled
__device__ fp16 g_kh[(size_t)BHd*Sd*HDd];                             // K hi only
__device__ fp16 g_vth[(size_t)BHd*HDd*Sd];                            // V^T hi: [HD][S]
__device__ float g_s[(size_t)BHd*Sd*Sd];                              // fp32 scores
__device__ fp16 g_ph[(size_t)BHd*Sd*Sd], g_pl[(size_t)BHd*Sd*Sd];    // probs hi/lo
__device__ fp16 g_omh[(size_t)Md*Dd], g_oml[(size_t)Md*Dd];          // attn out hi/lo

// ---------------- PTX helpers (sm_80-class only) ----------------
__device__ __forceinline__ uint32_t smem_u32(const void* p) {
    uint32_t a;
    asm("{ .reg .u64 t; cvta.to.shared.u64 t, %1; cvt.u32.u64 %0, t; }" : "=r"(a) : "l"(p));
    return a;
}
__device__ __forceinline__ void cpa16(uint32_t dst, const void* src) {
    asm volatile("cp.async.cg.shared.global [%0], [%1], 16;" :: "r"(dst), "l"(src) : "memory");
}
#define CP_COMMIT() asm volatile("cp.async.commit_group;" ::: "memory")
#define CP_WAIT0()  asm volatile("cp.async.wait_group 0;" ::: "memory")
#define CP_WAIT1()  asm volatile("cp.async.wait_group 1;" ::: "memory")

__device__ __forceinline__ void ldsm_x4(uint32_t (&r)[4], uint32_t addr) {
    asm volatile("ldmatrix.sync.aligned.m8n8.x4.shared.b16 {%0,%1,%2,%3}, [%4];"
                 : "=r"(r[0]), "=r"(r[1]), "=r"(r[2]), "=r"(r[3]) : "r"(addr));
}
__device__ __forceinline__ void mma16816(float (&d)[4], const uint32_t (&a)[4],
                                         uint32_t b0, uint32_t b1) {
    asm volatile("mma.sync.aligned.m16n8k16.row.col.f32.f16.f16.f32 "
                 "{%0,%1,%2,%3}, {%4,%5,%6,%7}, {%8,%9}, {%0,%1,%2,%3};"
                 : "+f"(d[0]), "+f"(d[1]), "+f"(d[2]), "+f"(d[3])
                 : "r"(a[0]), "r"(a[1]), "r"(a[2]), "r"(a[3]), "r"(b0), "r"(b1));
}

#define SWZ(x) ((x) ^ (((x) >> 3) & 0x70))

enum { EPI_Q = 0, EPI_K = 1, EPI_V = 2, EPI_SC = 3, EPI_AV = 4, EPI_OUT = 5 };

__device__ __forceinline__ void split_pair(float v0, float v1, __half2& h2, __half2& l2) {
    fp16 h0 = __float2half(v0), h1 = __float2half(v1);
    h2 = __halves2half2(h0, h1);
    l2 = __halves2half2(__float2half(v0 - __half2float(h0)),
                        __float2half(v1 - __half2float(h1)));
}

#define TILE   16384                   // 128x64 fp16 bytes
#define BUF    (3*TILE)                // Ah, Al, Bh
#define GSMEM  (1024 + 2*BUF)          // 99328 bytes

// ---- GEMM: C[128x128] = (Ah+Al)·Bh^T, 2-pass fp16 mma.sync, frag-pipelined ----
// A: [Mrows x K] k-major (ldA), B: [Nrows x K] k-major (ldB). K multiple of 64.
template<int EPI>
__global__ __launch_bounds__(256, 1)
void tc_gemm(const fp16* __restrict__ Ah, const fp16* __restrict__ Al,
             const fp16* __restrict__ Bh,
             float* __restrict__ Cf, fp16* __restrict__ Ch, fp16* __restrict__ Cl,
             int Kdim, int ldA, int ldB, long long sA, long long sB, float scale)
{
    extern __shared__ char smem[];
    const int bx = blockIdx.x, by = blockIdx.y, bz = blockIdx.z;
    if (EPI == EPI_SC && bx > by) return;   // causal block skip

    const int tid = threadIdx.x, wid = tid >> 5, lane = tid & 31;
    const int wm = wid >> 2, wn = wid & 3;  // 2x4 warp grid, warp tile 64x32
    const int m0 = by * 128, n0 = bx * 128;

    Ah += (size_t)bz * sA;  Al += (size_t)bz * sA;
    Bh += (size_t)bz * sB;

    int kend = Kdim;
    if (EPI == EPI_AV) kend = (Kdim < m0 + 128) ? Kdim : (m0 + 128);
    const int NC = kend >> 6;

    const uint32_t sb = (smem_u32(smem) + 1023) & ~1023u;

    // staging coords: 4 x 16B pieces per thread per 128x64 tile
    int prow[4], pcol[4]; uint32_t poff[4];
    #pragma unroll
    for (int t = 0; t < 4; t++) {
        int i = tid + t * 256;
        prow[t] = i >> 3; pcol[t] = (i & 7) * 8;
        poff[t] = SWZ((uint32_t)(prow[t] * 128 + pcol[t] * 2));
    }
    auto CPAC = [&](int c, int buf) {
        const int k0 = c * 64;
        const uint32_t b0 = sb + buf * BUF;
        #pragma unroll
        for (int t = 0; t < 4; t++) {
            const size_t ao = (size_t)(m0 + prow[t]) * ldA + k0 + pcol[t];
            const size_t bo = (size_t)(n0 + prow[t]) * ldB + k0 + pcol[t];
            cpa16(b0            + poff[t], Ah + ao);
            cpa16(b0 +   TILE   + poff[t], Al + ao);
            cpa16(b0 + 2*TILE   + poff[t], Bh + bo);
        }
    };

    // ldmatrix lane address components
    const int aRow  = lane & 15;
    const uint32_t aHi  = ((lane >> 4) & 1) * 16;
    const uint32_t aXor = (uint32_t)((aRow & 7) << 4);
    uint32_t aRowOff[4];
    #pragma unroll
    for (int mt = 0; mt < 4; mt++)
        aRowOff[mt] = (uint32_t)((wm * 64 + mt * 16 + aRow) * 128);

    const int bN    = (lane & 7) + ((lane >> 4) & 1) * 8;
    const uint32_t bHi  = ((lane >> 3) & 1) * 16;
    const uint32_t bXor = (uint32_t)((bN & 7) << 4);
    uint32_t bRowOff[2];
    #pragma unroll
    for (int ntp = 0; ntp < 2; ntp++)
        bRowOff[ntp] = (uint32_t)((wn * 32 + ntp * 16 + bN) * 128);

    float acc[4][4][4];
    #pragma unroll
    for (int i = 0; i < 4; i++)
        #pragma unroll
        for (int j = 0; j < 4; j++)
            #pragma unroll
            for (int q = 0; q < 4; q++) acc[i][j][q] = 0.0f;

    // double-buffered fragments (software pipeline over k16 steps)
    uint32_t ahf[2][4][4], alf[2][4][4], bhf[2][2][4];

    CPAC(0, 0); CP_COMMIT();

    for (int c = 0; c < NC; c++) {
        const int buf = c & 1;
        if (c + 1 < NC) { CPAC(c + 1, buf ^ 1); CP_COMMIT(); CP_WAIT1(); }
        else            { CP_WAIT0(); }
        __syncthreads();

        const uint32_t tAh = sb + buf * BUF;
        const uint32_t tAl = tAh + TILE;
        const uint32_t tBh = tAh + 2 * TILE;

        // prologue: fragments for kb=0
        {
            const uint32_t akc = aHi, bkc = bHi;
            #pragma unroll
            for (int mt = 0; mt < 4; mt++) {
                const uint32_t off = aRowOff[mt] + (akc ^ aXor);
                ldsm_x4(ahf[0][mt], tAh + off);
                ldsm_x4(alf[0][mt], tAl + off);
            }
            #pragma unroll
            for (int ntp = 0; ntp < 2; ntp++)
                ldsm_x4(bhf[0][ntp], tBh + bRowOff[ntp] + (bkc ^ bXor));
        }

        #pragma unroll
        for (int kb = 0; kb < 4; kb++) {
            const int s = kb & 1;
            if (kb < 3) {   // prefetch next k16 step's fragments
                const uint32_t akc = (uint32_t)((kb + 1) * 32) + aHi;
                const uint32_t bkc = (uint32_t)((kb + 1) * 32) + bHi;
                #pragma unroll
                for (int mt = 0; mt < 4; mt++) {
                    const uint32_t off = aRowOff[mt] + (akc ^ aXor);
                    ldsm_x4(ahf[s ^ 1][mt], tAh + off);
                    ldsm_x4(alf[s ^ 1][mt], tAl + off);
                }
                #pragma unroll
                for (int ntp = 0; ntp < 2; ntp++)
                    ldsm_x4(bhf[s ^ 1][ntp], tBh + bRowOff[ntp] + (bkc ^ bXor));
            }
            #pragma unroll
            for (int ntp = 0; ntp < 2; ntp++)
                #pragma unroll
                for (int mt = 0; mt < 4; mt++) {
                    mma16816(acc[mt][2*ntp],   ahf[s][mt], bhf[s][ntp][0], bhf[s][ntp][1]);
                    mma16816(acc[mt][2*ntp],   alf[s][mt], bhf[s][ntp][0], bhf[s][ntp][1]);
                    mma16816(acc[mt][2*ntp+1], ahf[s][mt], bhf[s][ntp][2], bhf[s][ntp][3]);
                    mma16816(acc[mt][2*ntp+1], alf[s][mt], bhf[s][ntp][2], bhf[s][ntp][3]);
                }
        }
        __syncthreads();
    }

    // ---------------- epilogue (register fragments) ----------------
    const int r0 = lane >> 2;
    const int cp2 = (lane & 3) * 2;

    #pragma unroll
    for (int mt = 0; mt < 4; mt++) {
        #pragma unroll
        for (int nt = 0; nt < 4; nt++) {
            const float* cc = acc[mt][nt];
            const int gmA = m0 + wm * 64 + mt * 16 + r0;
            const int gmB = gmA + 8;
            const int nl  = wn * 32 + nt * 8 + cp2;
            const int gn  = n0 + nl;

            if (EPI == EPI_SC) {
                float* dst = Cf + (size_t)bz * Sd * Sd;
                *reinterpret_cast<float2*>(dst + (size_t)gmA * Sd + gn) = make_float2(cc[0], cc[1]);
                *reinterpret_cast<float2*>(dst + (size_t)gmB * Sd + gn) = make_float2(cc[2], cc[3]);
            } else if (EPI == EPI_OUT) {
                *reinterpret_cast<float2*>(Cf + (size_t)gmA * Dd + gn) = make_float2(cc[0], cc[1]);
                *reinterpret_cast<float2*>(Cf + (size_t)gmB * Dd + gn) = make_float2(cc[2], cc[3]);
            } else if (EPI == EPI_AV) {
                const int b = bz >> 4, h = bz & 15;
                __half2 h2, l2;
                size_t baseA = ((size_t)(b * Sd + gmA)) * Dd + h * HDd + nl;
                size_t baseB = ((size_t)(b * Sd + gmB)) * Dd + h * HDd + nl;
                split_pair(cc[0], cc[1], h2, l2);
                *reinterpret_cast<__half2*>(Ch + baseA) = h2;
                *reinterpret_cast<__half2*>(Cl + baseA) = l2;
                split_pair(cc[2], cc[3], h2, l2);
                *reinterpret_cast<__half2*>(Ch + baseB) = h2;
                *reinterpret_cast<__half2*>(Cl + baseB) = l2;
            } else {
                const int h  = gn >> 7;
                const int hd = gn & (HDd - 1);
                #pragma unroll
                for (int half = 0; half < 2; half++) {
                    const int gm = half ? gmB : gmA;
                    float v0 = cc[half * 2], v1 = cc[half * 2 + 1];
                    const int b = gm >> 11, s = gm & (Sd - 1);
                    const size_t base = (((size_t)(b * Hd + h)) * Sd + s) * HDd + hd;
                    if (EPI == EPI_K || EPI == EPI_V)
                        *reinterpret_cast<float2*>(Cf + base) = make_float2(v0, v1);
                    if (EPI == EPI_Q) {
                        // fold attention scale into Q
                        v0 *= scale; v1 *= scale;
                        __half2 h2, l2;
                        split_pair(v0, v1, h2, l2);
                        *reinterpret_cast<__half2*>(Ch + base) = h2;
                        *reinterpret_cast<__half2*>(Cl + base) = l2;
                    } else if (EPI == EPI_K) {
                        *reinterpret_cast<__half2*>(Ch + base) =
                            __halves2half2(__float2half(v0), __float2half(v1));
                    } else { // EPI_V: transposed hi-only scratch [b,h][hd][s]
                        const size_t ti = (((size_t)(b * Hd + h)) * HDd + hd) * Sd + s;
                        Ch[ti]      = __float2half(v0);
                        Ch[ti + Sd] = __float2half(v1);
                    }
                }
            }
        }
    }
}

// ---------------- causal softmax: fp32 scores -> fp16 hi/lo probs ----------------
__global__ void softmax_kernel(const float* __restrict__ S,
                               fp16* __restrict__ Ph, fp16* __restrict__ Pl)
{
    const int row = blockIdx.x, bh = blockIdx.y, tid = threadIdx.x;
    const float* p = S + (size_t)bh * Sd * Sd + (size_t)row * Sd;
    fp16* ph = Ph + (size_t)bh * Sd * Sd + (size_t)row * Sd;
    fp16* pl = Pl + (size_t)bh * Sd * Sd + (size_t)row * Sd;
    const int n = row + 1;
    const int kmax = ((row >> 7) + 1) << 7;   // zero-fill to 128-block boundary (AV clamp)

    __shared__ float red[256];
    float v[8]; int cnt = 0; float mx = -FLT_MAX;
    for (int j = tid; j < n; j += 256) { float x = p[j]; v[cnt++] = x; mx = fmaxf(mx, x); }
    red[tid] = mx; __syncthreads();
    #pragma unroll
    for (int s2 = 128; s2 > 0; s2 >>= 1) { if (tid < s2) red[tid] = fmaxf(red[tid], red[tid + s2]); __syncthreads(); }
    mx = red[0]; __syncthreads();

    float sum = 0.0f;
    for (int c = 0; c < cnt; c++) { v[c] = expf(v[c] - mx); sum += v[c]; }
    red[tid] = sum; __syncthreads();
    #pragma unroll
    for (int s2 = 128; s2 > 0; s2 >>= 1) { if (tid < s2) red[tid] += red[tid + s2]; __syncthreads(); }
    const float inv = 1.0f / red[0];

    cnt = 0;
    for (int j = tid; j < kmax; j += 256) {
        float val = (j < n) ? v[cnt++] * inv : 0.0f;
        fp16 hh = __float2half(val);
        ph[j] = hh;
        pl[j] = __float2half(val - __half2float(hh));
    }
}

// ---------------- x: fp32 -> (fp16 hi, fp16 lo) ----------------
__global__ void split_x_kernel(const float4* __restrict__ in,
                               __half2* __restrict__ hi, __half2* __restrict__ lo, int n4)
{
    int i = blockIdx.x * 256 + threadIdx.x;
    if (i >= n4) return;
    float4 x = in[i];
    __half2 h2, l2;
    split_pair(x.x, x.y, h2, l2); hi[2*i]   = h2; lo[2*i]   = l2;
    split_pair(x.z, x.w, h2, l2); hi[2*i+1] = h2; lo[2*i+1] = l2;
}

// ---------------- all 4 weights: fp32 -> fp16 hi (fused, one launch) ----------------
__global__ void split_w4_kernel(const float4* __restrict__ wq, const float4* __restrict__ wk,
                                const float4* __restrict__ wv, const float4* __restrict__ wo,
                                __half2* __restrict__ dq, __half2* __restrict__ dk,
                                __half2* __restrict__ dv, __half2* __restrict__ dwo, int n4each)
{
    int i = blockIdx.x * 256 + threadIdx.x;
    int w = i / n4each;
    if (w >= 4) return;
    int j = i - w * n4each;
    const float4* src = (w == 0) ? wq : (w == 1) ? wk : (w == 2) ? wv : wo;
    __half2* dst      = (w == 0) ? dq : (w == 1) ? dk : (w == 2) ? dv : dwo;
    float4 x = src[j];
    dst[2*j]   = __halves2half2(__float2half(x.x), __float2half(x.y));
    dst[2*j+1] = __halves2half2(__float2half(x.z), __float2half(x.w));
}

extern "C" void kernel_launch(void* const* d_in, const int* in_sizes, int n_in,
                              void* d_out, int out_size)
{
    const float* x  = (const float*)d_in[0];
    const float* Wq = (const float*)d_in[1];
    const float* Wk = (const float*)d_in[2];
    const float* Wv = (const float*)d_in[3];
    const float* Wo = (const float*)d_in[4];

    float* out  = (float*)d_out;
    float* kout = out  + (size_t)Md * Dd;
    float* vout = kout + (size_t)Md * Dd;

    fp16 *xh,*xl,*wqh,*wkh,*wvh,*woh;
    fp16 *qh,*ql,*kh,*vth,*pph,*ppl,*omh,*oml;
    float* sp;
    cudaGetSymbolAddress((void**)&xh, g_xh);   cudaGetSymbolAddress((void**)&xl, g_xl);
    cudaGetSymbolAddress((void**)&wqh, g_wqh); cudaGetSymbolAddress((void**)&wkh, g_wkh);
    cudaGetSymbolAddress((void**)&wvh, g_wvh); cudaGetSymbolAddress((void**)&woh, g_woh);
    cudaGetSymbolAddress((void**)&qh, g_qh);   cudaGetSymbolAddress((void**)&ql, g_ql);
    cudaGetSymbolAddress((void**)&kh, g_kh);   cudaGetSymbolAddress((void**)&vth, g_vth);
    cudaGetSymbolAddress((void**)&pph, g_ph);  cudaGetSymbolAddress((void**)&ppl, g_pl);
    cudaGetSymbolAddress((void**)&omh, g_omh); cudaGetSymbolAddress((void**)&oml, g_oml);
    cudaGetSymbolAddress((void**)&sp, g_s);

    cudaFuncSetAttribute(tc_gemm<EPI_Q>,   cudaFuncAttributeMaxDynamicSharedMemorySize, GSMEM);
    cudaFuncSetAttribute(tc_gemm<EPI_K>,   cudaFuncAttributeMaxDynamicSharedMemorySize, GSMEM);
    cudaFuncSetAttribute(tc_gemm<EPI_V>,   cudaFuncAttributeMaxDynamicSharedMemorySize, GSMEM);
    cudaFuncSetAttribute(tc_gemm<EPI_SC>,  cudaFuncAttributeMaxDynamicSharedMemorySize, GSMEM);
    cudaFuncSetAttribute(tc_gemm<EPI_AV>,  cudaFuncAttributeMaxDynamicSharedMemorySize, GSMEM);
    cudaFuncSetAttribute(tc_gemm<EPI_OUT>, cudaFuncAttributeMaxDynamicSharedMemorySize, GSMEM);

    const float scale = 1.0f / sqrtf((float)HDd);
    dim3 blk(256);

    // launch 0: split x (hi/lo); launch 1: all 4 weights (hi) — keeps SC at ncu -s 5
    split_x_kernel <<<(Md*Dd/4 + 255)/256, 256>>>((const float4*)x, (__half2*)xh, (__half2*)xl, Md*Dd/4);
    split_w4_kernel<<<(4*(Dd*Dd/4) + 255)/256, 256>>>((const float4*)Wq, (const float4*)Wk,
                                                      (const float4*)Wv, (const float4*)Wo,
                                                      (__half2*)wqh, (__half2*)wkh,
                                                      (__half2*)wvh, (__half2*)woh, Dd*Dd/4);

    // 1) QKV projections (NT, 2-pass); Q epilogue folds the attention scale
    dim3 gP(Dd/128, Md/128, 1);
    tc_gemm<EPI_Q><<<gP, blk, GSMEM>>>(xh, xl, wqh, nullptr, qh, ql, Dd, Dd, Dd, 0, 0, scale);
    tc_gemm<EPI_K><<<gP, blk, GSMEM>>>(xh, xl, wkh, kout,   kh, nullptr, Dd, Dd, Dd, 0, 0, 1.0f);
    tc_gemm<EPI_V><<<gP, blk, GSMEM>>>(xh, xl, wvh, vout,   vth, nullptr, Dd, Dd, Dd, 0, 0, 1.0f);

    // 2) scores (NT, 2-pass, causal block-skip): (Qh+Ql)·Kh^T  (scale pre-folded)
    dim3 gS(Sd/128, Sd/128, BHd);
    tc_gemm<EPI_SC><<<gS, blk, GSMEM>>>(qh, ql, kh, sp, nullptr, nullptr,
                                        HDd, HDd, HDd,
                                        (long long)Sd*HDd, (long long)Sd*HDd, 1.0f);

    // 3) softmax (fp32 in, fp16 hi/lo out, zero-filled to block boundary)
    softmax_kernel<<<dim3(Sd, BHd), 256>>>(sp, pph, ppl);

    // 4) P · V (2-pass, k-clamped per row tile), via V^T hi so B is k-major
    dim3 gAV(1, Sd/128, BHd);
    tc_gemm<EPI_AV><<<gAV, blk, GSMEM>>>(pph, ppl, vth, nullptr, omh, oml,
                                         Sd, Sd, Sd,
                                         (long long)Sd*Sd, (long long)HDd*Sd, 1.0f);

    // 5) output projection (NT, 2-pass) -> fp32 out
    dim3 gO(Dd/128, Md/128, 1);
    tc_gemm<EPI_OUT><<<gO, blk, GSMEM>>>(omh, oml, woh, out, nullptr, nullptr,
                                         Dd, Dd, Dd, 0, 0, 1.0f);
}

// round 10
// speedup vs baseline: 3.8547x; 1.0526x over previous
#include <cuda_runtime.h>
#include <cuda_fp16.h>
#include <math.h>
#include <float.h>
#include <stdint.h>

#define Bd  2
#define Sd  2048
#define Dd  2048
#define Hd  16
#define HDd 128
#define Md  (Bd*Sd)
#define BHd (Bd*Hd)

typedef __half fp16;

// ---------------- scratch (__device__ globals; allocation-free rule) ----------------
__device__ fp16 g_xh[(size_t)Md*Dd];                                  // x hi only
__device__ fp16 g_wqh[(size_t)Dd*Dd], g_wql[(size_t)Dd*Dd];           // weights hi/lo
__device__ fp16 g_wkh[(size_t)Dd*Dd], g_wkl[(size_t)Dd*Dd];
__device__ fp16 g_wvh[(size_t)Dd*Dd], g_wvl[(size_t)Dd*Dd];
__device__ fp16 g_woh[(size_t)Dd*Dd], g_wol[(size_t)Dd*Dd];
__device__ fp16 g_qh[(size_t)BHd*Sd*HDd], g_ql[(size_t)BHd*Sd*HDd];   // Q pre-scaled hi/lo
__device__ fp16 g_kh[(size_t)BHd*Sd*HDd];                             // K hi
__device__ fp16 g_vth[(size_t)BHd*HDd*Sd];                            // V^T hi: [HD][S]
__device__ float g_s[(size_t)BHd*Sd*Sd];                              // fp32 scores
__device__ fp16 g_ph[(size_t)BHd*Sd*Sd], g_pl[(size_t)BHd*Sd*Sd];     // probs hi/lo
__device__ fp16 g_omh[(size_t)Md*Dd], g_oml[(size_t)Md*Dd];           // attn out hi/lo

// ---------------- PTX helpers (sm_80-class only) ----------------
__device__ __forceinline__ uint32_t smem_u32(const void* p) {
    uint32_t a;
    asm("{ .reg .u64 t; cvta.to.shared.u64 t, %1; cvt.u32.u64 %0, t; }" : "=r"(a) : "l"(p));
    return a;
}
__device__ __forceinline__ void cpa16(uint32_t dst, const void* src) {
    asm volatile("cp.async.cg.shared.global [%0], [%1], 16;" :: "r"(dst), "l"(src) : "memory");
}
#define CP_COMMIT() asm volatile("cp.async.commit_group;" ::: "memory")
#define CP_WAIT0()  asm volatile("cp.async.wait_group 0;" ::: "memory")
#define CP_WAIT1()  asm volatile("cp.async.wait_group 1;" ::: "memory")

__device__ __forceinline__ void ldsm_x4(uint32_t (&r)[4], uint32_t addr) {
    asm volatile("ldmatrix.sync.aligned.m8n8.x4.shared.b16 {%0,%1,%2,%3}, [%4];"
                 : "=r"(r[0]), "=r"(r[1]), "=r"(r[2]), "=r"(r[3]) : "r"(addr));
}
__device__ __forceinline__ void mma16816(float (&d)[4], const uint32_t (&a)[4],
                                         uint32_t b0, uint32_t b1) {
    asm volatile("mma.sync.aligned.m16n8k16.row.col.f32.f16.f16.f32 "
                 "{%0,%1,%2,%3}, {%4,%5,%6,%7}, {%8,%9}, {%0,%1,%2,%3};"
                 : "+f"(d[0]), "+f"(d[1]), "+f"(d[2]), "+f"(d[3])
                 : "r"(a[0]), "r"(a[1]), "r"(a[2]), "r"(a[3]), "r"(b0), "r"(b1));
}

#define SWZ(x) ((x) ^ (((x) >> 3) & 0x70))

enum { EPI_Q = 0, EPI_K = 1, EPI_V = 2, EPI_SC = 3, EPI_AV = 4, EPI_OUT = 5 };

__device__ __forceinline__ void split_pair(float v0, float v1, __half2& h2, __half2& l2) {
    fp16 h0 = __float2half(v0), h1 = __float2half(v1);
    h2 = __halves2half2(h0, h1);
    l2 = __halves2half2(__float2half(v0 - __half2float(h0)),
                        __float2half(v1 - __half2float(h1)));
}

// ================= projection GEMM: CTA 128x256, warp 64x64, split-B ==============
// C = Ah · (Bh + Bl)^T.  A: [M x K] k-major hi-only. B: [N x K] k-major hi/lo.
#define TA2    16384                   // A tile 128x64 fp16
#define TB2    32768                   // B tile 256x64 fp16
#define BUF2   (TA2 + 2*TB2)           // 80 KB
#define GSMEM2 (1024 + 2*BUF2)         // 164864 B

template<int EPI>
__global__ __launch_bounds__(256, 1)
void tc_gemm_w(const fp16* __restrict__ Ah,
               const fp16* __restrict__ Bh, const fp16* __restrict__ Bl,
               float* __restrict__ Cf, fp16* __restrict__ Ch, fp16* __restrict__ Cl,
               int Kdim, int ldA, int ldB, float scale)
{
    extern __shared__ char smem[];
    const int bx = blockIdx.x, by = blockIdx.y;
    const int tid = threadIdx.x, wid = tid >> 5, lane = tid & 31;
    const int wm = wid >> 2, wn = wid & 3;   // 2x4 grid, warp tile 64x64
    const int m0 = by * 128, n0 = bx * 256;
    const int NC = Kdim >> 6;

    const uint32_t sb = (smem_u32(smem) + 1023) & ~1023u;

    // staging: A 4 pieces/thread, B 8 pieces/thread per copy
    int ar[4], ac[4]; uint32_t ao_[4];
    #pragma unroll
    for (int t = 0; t < 4; t++) {
        int i = tid + t * 256;
        ar[t] = i >> 3; ac[t] = (i & 7) * 8;
        ao_[t] = SWZ((uint32_t)(ar[t] * 128 + ac[t] * 2));
    }
    int br[8], bc[8]; uint32_t bo_[8];
    #pragma unroll
    for (int t = 0; t < 8; t++) {
        int i = tid + t * 256;
        br[t] = i >> 3; bc[t] = (i & 7) * 8;
        bo_[t] = SWZ((uint32_t)(br[t] * 128 + bc[t] * 2));
    }
    auto CPAC = [&](int c, int buf) {
        const int k0 = c * 64;
        const uint32_t b0 = sb + buf * BUF2;
        #pragma unroll
        for (int t = 0; t < 4; t++)
            cpa16(b0 + ao_[t], Ah + (size_t)(m0 + ar[t]) * ldA + k0 + ac[t]);
        #pragma unroll
        for (int t = 0; t < 8; t++) {
            const size_t bo = (size_t)(n0 + br[t]) * ldB + k0 + bc[t];
            cpa16(b0 + TA2       + bo_[t], Bh + bo);
            cpa16(b0 + TA2 + TB2 + bo_[t], Bl + bo);
        }
    };

    const int aRow  = lane & 15;
    const uint32_t aHi  = ((lane >> 4) & 1) * 16;
    const uint32_t aXor = (uint32_t)((aRow & 7) << 4);
    uint32_t aRowOff[4];
    #pragma unroll
    for (int mt = 0; mt < 4; mt++)
        aRowOff[mt] = (uint32_t)((wm * 64 + mt * 16 + aRow) * 128);

    const int bN    = (lane & 7) + ((lane >> 4) & 1) * 8;
    const uint32_t bHi  = ((lane >> 3) & 1) * 16;
    const uint32_t bXor = (uint32_t)((bN & 7) << 4);
    uint32_t bRowOff[4];
    #pragma unroll
    for (int ntp = 0; ntp < 4; ntp++)
        bRowOff[ntp] = (uint32_t)((wn * 64 + ntp * 16 + bN) * 128);

    float acc[4][8][4];
    #pragma unroll
    for (int i = 0; i < 4; i++)
        #pragma unroll
        for (int j = 0; j < 8; j++)
            #pragma unroll
            for (int q = 0; q < 4; q++) acc[i][j][q] = 0.0f;

    CPAC(0, 0); CP_COMMIT();

    for (int c = 0; c < NC; c++) {
        const int buf = c & 1;
        if (c + 1 < NC) { CPAC(c + 1, buf ^ 1); CP_COMMIT(); CP_WAIT1(); }
        else            { CP_WAIT0(); }
        __syncthreads();

        const uint32_t tA  = sb + buf * BUF2;
        const uint32_t tBh = tA + TA2;
        const uint32_t tBl = tBh + TB2;

        #pragma unroll
        for (int kb = 0; kb < 4; kb++) {
            const uint32_t akc = (uint32_t)(kb * 32) + aHi;
            const uint32_t bkc = (uint32_t)(kb * 32) + bHi;

            uint32_t ah[4][4];
            #pragma unroll
            for (int mt = 0; mt < 4; mt++)
                ldsm_x4(ah[mt], tA + aRowOff[mt] + (akc ^ aXor));

            #pragma unroll
            for (int ntp = 0; ntp < 4; ntp++) {
                uint32_t bh[4], bl[4];
                const uint32_t off = bRowOff[ntp] + (bkc ^ bXor);
                ldsm_x4(bh, tBh + off);
                ldsm_x4(bl, tBl + off);
                #pragma unroll
                for (int mt = 0; mt < 4; mt++) {
                    mma16816(acc[mt][2*ntp],   ah[mt], bh[0], bh[1]);
                    mma16816(acc[mt][2*ntp],   ah[mt], bl[0], bl[1]);
                    mma16816(acc[mt][2*ntp+1], ah[mt], bh[2], bh[3]);
                    mma16816(acc[mt][2*ntp+1], ah[mt], bl[2], bl[3]);
                }
            }
        }
        __syncthreads();
    }

    // ---------------- epilogue ----------------
    const int r0 = lane >> 2;
    const int cp2 = (lane & 3) * 2;

    #pragma unroll
    for (int mt = 0; mt < 4; mt++) {
        #pragma unroll
        for (int nt = 0; nt < 8; nt++) {
            const float* cc = acc[mt][nt];
            const int gmA = m0 + wm * 64 + mt * 16 + r0;
            const int gmB = gmA + 8;
            const int nl  = wn * 64 + nt * 8 + cp2;
            const int gn  = n0 + nl;

            if (EPI == EPI_OUT) {
                *reinterpret_cast<float2*>(Cf + (size_t)gmA * Dd + gn) = make_float2(cc[0], cc[1]);
                *reinterpret_cast<float2*>(Cf + (size_t)gmB * Dd + gn) = make_float2(cc[2], cc[3]);
            } else {
                const int h  = gn >> 7;
                const int hd = gn & (HDd - 1);
                #pragma unroll
                for (int half = 0; half < 2; half++) {
                    const int gm = half ? gmB : gmA;
                    float v0 = cc[half * 2], v1 = cc[half * 2 + 1];
                    const int b = gm >> 11, s = gm & (Sd - 1);
                    const size_t base = (((size_t)(b * Hd + h)) * Sd + s) * HDd + hd;
                    if (EPI == EPI_K || EPI == EPI_V)
                        *reinterpret_cast<float2*>(Cf + base) = make_float2(v0, v1);
                    if (EPI == EPI_Q) {
                        v0 *= scale; v1 *= scale;
                        __half2 h2, l2;
                        split_pair(v0, v1, h2, l2);
                        *reinterpret_cast<__half2*>(Ch + base) = h2;
                        *reinterpret_cast<__half2*>(Cl + base) = l2;
                    } else if (EPI == EPI_K) {
                        *reinterpret_cast<__half2*>(Ch + base) =
                            __halves2half2(__float2half(v0), __float2half(v1));
                    } else if (EPI == EPI_V) {
                        const size_t ti = (((size_t)(b * Hd + h)) * HDd + hd) * Sd + s;
                        Ch[ti]      = __float2half(v0);
                        Ch[ti + Sd] = __float2half(v1);
                    }
                }
            }
        }
    }
}

// ========== attention GEMM (R8-proven): CTA 128x128, warp 64x32, split-A ==========
#define TILE   16384
#define BUF    (3*TILE)
#define GSMEM  (1024 + 2*BUF)

template<int EPI>
__global__ __launch_bounds__(256, 1)
void tc_gemm(const fp16* __restrict__ Ah, const fp16* __restrict__ Al,
             const fp16* __restrict__ Bh,
             float* __restrict__ Cf, fp16* __restrict__ Ch, fp16* __restrict__ Cl,
             int Kdim, int ldA, int ldB, long long sA, long long sB)
{
    extern __shared__ char smem[];
    const int bx = blockIdx.x, by = blockIdx.y, bz = blockIdx.z;
    if (EPI == EPI_SC && bx > by) return;   // causal block skip

    const int tid = threadIdx.x, wid = tid >> 5, lane = tid & 31;
    const int wm = wid >> 2, wn = wid & 3;
    const int m0 = by * 128, n0 = bx * 128;

    Ah += (size_t)bz * sA;  Al += (size_t)bz * sA;
    Bh += (size_t)bz * sB;

    int kend = Kdim;
    if (EPI == EPI_AV) kend = (Kdim < m0 + 128) ? Kdim : (m0 + 128);
    const int NC = kend >> 6;

    const uint32_t sb = (smem_u32(smem) + 1023) & ~1023u;

    int prow[4], pcol[4]; uint32_t poff[4];
    #pragma unroll
    for (int t = 0; t < 4; t++) {
        int i = tid + t * 256;
        prow[t] = i >> 3; pcol[t] = (i & 7) * 8;
        poff[t] = SWZ((uint32_t)(prow[t] * 128 + pcol[t] * 2));
    }
    auto CPAC = [&](int c, int buf) {
        const int k0 = c * 64;
        const uint32_t b0 = sb + buf * BUF;
        #pragma unroll
        for (int t = 0; t < 4; t++) {
            const size_t ao = (size_t)(m0 + prow[t]) * ldA + k0 + pcol[t];
            const size_t bo = (size_t)(n0 + prow[t]) * ldB + k0 + pcol[t];
            cpa16(b0          + poff[t], Ah + ao);
            cpa16(b0 + TILE   + poff[t], Al + ao);
            cpa16(b0 + 2*TILE + poff[t], Bh + bo);
        }
    };

    const int aRow  = lane & 15;
    const uint32_t aHi  = ((lane >> 4) & 1) * 16;
    const uint32_t aXor = (uint32_t)((aRow & 7) << 4);
    uint32_t aRowOff[4];
    #pragma unroll
    for (int mt = 0; mt < 4; mt++)
        aRowOff[mt] = (uint32_t)((wm * 64 + mt * 16 + aRow) * 128);

    const int bN    = (lane & 7) + ((lane >> 4) & 1) * 8;
    const uint32_t bHi  = ((lane >> 3) & 1) * 16;
    const uint32_t bXor = (uint32_t)((bN & 7) << 4);
    uint32_t bRowOff[2];
    #pragma unroll
    for (int ntp = 0; ntp < 2; ntp++)
        bRowOff[ntp] = (uint32_t)((wn * 32 + ntp * 16 + bN) * 128);

    float acc[4][4][4];
    #pragma unroll
    for (int i = 0; i < 4; i++)
        #pragma unroll
        for (int j = 0; j < 4; j++)
            #pragma unroll
            for (int q = 0; q < 4; q++) acc[i][j][q] = 0.0f;

    CPAC(0, 0); CP_COMMIT();

    for (int c = 0; c < NC; c++) {
        const int buf = c & 1;
        if (c + 1 < NC) { CPAC(c + 1, buf ^ 1); CP_COMMIT(); CP_WAIT1(); }
        else            { CP_WAIT0(); }
        __syncthreads();

        const uint32_t tAh = sb + buf * BUF;
        const uint32_t tAl = tAh + TILE;
        const uint32_t tBh = tAh + 2 * TILE;

        #pragma unroll
        for (int kb = 0; kb < 4; kb++) {
            const uint32_t akc = (uint32_t)(kb * 32) + aHi;
            const uint32_t bkc = (uint32_t)(kb * 32) + bHi;

            uint32_t ah[4][4], al[4][4];
            #pragma unroll
            for (int mt = 0; mt < 4; mt++) {
                const uint32_t off = aRowOff[mt] + (akc ^ aXor);
                ldsm_x4(ah[mt], tAh + off);
                ldsm_x4(al[mt], tAl + off);
            }
            #pragma unroll
            for (int ntp = 0; ntp < 2; ntp++) {
                uint32_t bh[4];
                ldsm_x4(bh, tBh + bRowOff[ntp] + (bkc ^ bXor));
                #pragma unroll
                for (int mt = 0; mt < 4; mt++) {
                    mma16816(acc[mt][2*ntp],   ah[mt], bh[0], bh[1]);
                    mma16816(acc[mt][2*ntp],   al[mt], bh[0], bh[1]);
                    mma16816(acc[mt][2*ntp+1], ah[mt], bh[2], bh[3]);
                    mma16816(acc[mt][2*ntp+1], al[mt], bh[2], bh[3]);
                }
            }
        }
        __syncthreads();
    }

    const int r0 = lane >> 2;
    const int cp2 = (lane & 3) * 2;

    #pragma unroll
    for (int mt = 0; mt < 4; mt++) {
        #pragma unroll
        for (int nt = 0; nt < 4; nt++) {
            const float* cc = acc[mt][nt];
            const int gmA = m0 + wm * 64 + mt * 16 + r0;
            const int gmB = gmA + 8;
            const int nl  = wn * 32 + nt * 8 + cp2;
            const int gn  = n0 + nl;

            if (EPI == EPI_SC) {
                float* dst = Cf + (size_t)bz * Sd * Sd;
                *reinterpret_cast<float2*>(dst + (size_t)gmA * Sd + gn) = make_float2(cc[0], cc[1]);
                *reinterpret_cast<float2*>(dst + (size_t)gmB * Sd + gn) = make_float2(cc[2], cc[3]);
            } else { // EPI_AV
                const int b = bz >> 4, h = bz & 15;
                __half2 h2, l2;
                size_t baseA = ((size_t)(b * Sd + gmA)) * Dd + h * HDd + nl;
                size_t baseB = ((size_t)(b * Sd + gmB)) * Dd + h * HDd + nl;
                split_pair(cc[0], cc[1], h2, l2);
                *reinterpret_cast<__half2*>(Ch + baseA) = h2;
                *reinterpret_cast<__half2*>(Cl + baseA) = l2;
                split_pair(cc[2], cc[3], h2, l2);
                *reinterpret_cast<__half2*>(Ch + baseB) = h2;
                *reinterpret_cast<__half2*>(Cl + baseB) = l2;
            }
        }
    }
}

// ---------------- causal softmax: fp32 scores -> fp16 hi/lo probs ----------------
__global__ void softmax_kernel(const float* __restrict__ S,
                               fp16* __restrict__ Ph, fp16* __restrict__ Pl)
{
    const int row = blockIdx.x, bh = blockIdx.y, tid = threadIdx.x;
    const float* p = S + (size_t)bh * Sd * Sd + (size_t)row * Sd;
    fp16* ph = Ph + (size_t)bh * Sd * Sd + (size_t)row * Sd;
    fp16* pl = Pl + (size_t)bh * Sd * Sd + (size_t)row * Sd;
    const int n = row + 1;
    const int kmax = ((row >> 7) + 1) << 7;

    __shared__ float red[256];
    float v[8]; int cnt = 0; float mx = -FLT_MAX;
    for (int j = tid; j < n; j += 256) { float x = p[j]; v[cnt++] = x; mx = fmaxf(mx, x); }
    red[tid] = mx; __syncthreads();
    #pragma unroll
    for (int s2 = 128; s2 > 0; s2 >>= 1) { if (tid < s2) red[tid] = fmaxf(red[tid], red[tid + s2]); __syncthreads(); }
    mx = red[0]; __syncthreads();

    float sum = 0.0f;
    for (int c = 0; c < cnt; c++) { v[c] = expf(v[c] - mx); sum += v[c]; }
    red[tid] = sum; __syncthreads();
    #pragma unroll
    for (int s2 = 128; s2 > 0; s2 >>= 1) { if (tid < s2) red[tid] += red[tid + s2]; __syncthreads(); }
    const float inv = 1.0f / red[0];

    cnt = 0;
    for (int j = tid; j < kmax; j += 256) {
        float val = (j < n) ? v[cnt++] * inv : 0.0f;
        fp16 hh = __float2half(val);
        ph[j] = hh;
        pl[j] = __float2half(val - __half2float(hh));
    }
}

// ---------------- x: fp32 -> fp16 hi only ----------------
__global__ void split_x_kernel(const float4* __restrict__ in, __half2* __restrict__ hi, int n4)
{
    int i = blockIdx.x * 256 + threadIdx.x;
    if (i >= n4) return;
    float4 x = in[i];
    hi[2*i]   = __halves2half2(__float2half(x.x), __float2half(x.y));
    hi[2*i+1] = __halves2half2(__float2half(x.z), __float2half(x.w));
}

// ---------------- all 4 weights: fp32 -> fp16 hi/lo (fused, one launch) ----------------
__global__ void split_w4_kernel(const float4* __restrict__ wq, const float4* __restrict__ wk,
                                const float4* __restrict__ wv, const float4* __restrict__ wo,
                                __half2* __restrict__ qh2, __half2* __restrict__ ql2,
                                __half2* __restrict__ kh2, __half2* __restrict__ kl2,
                                __half2* __restrict__ vh2, __half2* __restrict__ vl2,
                                __half2* __restrict__ oh2, __half2* __restrict__ ol2, int n4each)
{
    int i = blockIdx.x * 256 + threadIdx.x;
    int w = i / n4each;
    if (w >= 4) return;
    int j = i - w * n4each;
    const float4* src = (w == 0) ? wq : (w == 1) ? wk : (w == 2) ? wv : wo;
    __half2* dh = (w == 0) ? qh2 : (w == 1) ? kh2 : (w == 2) ? vh2 : oh2;
    __half2* dl = (w == 0) ? ql2 : (w == 1) ? kl2 : (w == 2) ? vl2 : ol2;
    float4 x = src[j];
    __half2 h2, l2;
    split_pair(x.x, x.y, h2, l2); dh[2*j]   = h2; dl[2*j]   = l2;
    split_pair(x.z, x.w, h2, l2); dh[2*j+1] = h2; dl[2*j+1] = l2;
}

extern "C" void kernel_launch(void* const* d_in, const int* in_sizes, int n_in,
                              void* d_out, int out_size)
{
    const float* x  = (const float*)d_in[0];
    const float* Wq = (const float*)d_in[1];
    const float* Wk = (const float*)d_in[2];
    const float* Wv = (const float*)d_in[3];
    const float* Wo = (const float*)d_in[4];

    float* out  = (float*)d_out;
    float* kout = out  + (size_t)Md * Dd;
    float* vout = kout + (size_t)Md * Dd;

    fp16 *xh,*wqh,*wql,*wkh,*wkl,*wvh,*wvl,*woh,*wol;
    fp16 *qh,*ql,*kh,*vth,*pph,*ppl,*omh,*oml;
    float* sp;
    cudaGetSymbolAddress((void**)&xh, g_xh);
    cudaGetSymbolAddress((void**)&wqh, g_wqh); cudaGetSymbolAddress((void**)&wql, g_wql);
    cudaGetSymbolAddress((void**)&wkh, g_wkh); cudaGetSymbolAddress((void**)&wkl, g_wkl);
    cudaGetSymbolAddress((void**)&wvh, g_wvh); cudaGetSymbolAddress((void**)&wvl, g_wvl);
    cudaGetSymbolAddress((void**)&woh, g_woh); cudaGetSymbolAddress((void**)&wol, g_wol);
    cudaGetSymbolAddress((void**)&qh, g_qh);   cudaGetSymbolAddress((void**)&ql, g_ql);
    cudaGetSymbolAddress((void**)&kh, g_kh);   cudaGetSymbolAddress((void**)&vth, g_vth);
    cudaGetSymbolAddress((void**)&pph, g_ph);  cudaGetSymbolAddress((void**)&ppl, g_pl);
    cudaGetSymbolAddress((void**)&omh, g_omh); cudaGetSymbolAddress((void**)&oml, g_oml);
    cudaGetSymbolAddress((void**)&sp, g_s);

    cudaFuncSetAttribute(tc_gemm_w<EPI_Q>,   cudaFuncAttributeMaxDynamicSharedMemorySize, GSMEM2);
    cudaFuncSetAttribute(tc_gemm_w<EPI_K>,   cudaFuncAttributeMaxDynamicSharedMemorySize, GSMEM2);
    cudaFuncSetAttribute(tc_gemm_w<EPI_V>,   cudaFuncAttributeMaxDynamicSharedMemorySize, GSMEM2);
    cudaFuncSetAttribute(tc_gemm_w<EPI_OUT>, cudaFuncAttributeMaxDynamicSharedMemorySize, GSMEM2);
    cudaFuncSetAttribute(tc_gemm<EPI_SC>,    cudaFuncAttributeMaxDynamicSharedMemorySize, GSMEM);
    cudaFuncSetAttribute(tc_gemm<EPI_AV>,    cudaFuncAttributeMaxDynamicSharedMemorySize, GSMEM);

    const float scale = 1.0f / sqrtf((float)HDd);
    dim3 blk(256);

    // splits: x hi; weights hi/lo (fused)
    split_x_kernel <<<(Md*Dd/4 + 255)/256, 256>>>((const float4*)x, (__half2*)xh, Md*Dd/4);
    split_w4_kernel<<<(4*(Dd*Dd/4) + 255)/256, 256>>>(
        (const float4*)Wq, (const float4*)Wk, (const float4*)Wv, (const float4*)Wo,
        (__half2*)wqh, (__half2*)wql, (__half2*)wkh, (__half2*)wkl,
        (__half2*)wvh, (__half2*)wvl, (__half2*)woh, (__half2*)wol, Dd*Dd/4);

    // 1) QKV projections (split-B, CTA 128x256); Q epilogue folds attention scale
    dim3 gP(Dd/256, Md/128, 1);
    tc_gemm_w<EPI_Q><<<gP, blk, GSMEM2>>>(xh, wqh, wql, nullptr, qh, ql, Dd, Dd, Dd, scale);
    tc_gemm_w<EPI_K><<<gP, blk, GSMEM2>>>(xh, wkh, wkl, kout,   kh, nullptr, Dd, Dd, Dd, 1.0f);
    tc_gemm_w<EPI_V><<<gP, blk, GSMEM2>>>(xh, wvh, wvl, vout,   vth, nullptr, Dd, Dd, Dd, 1.0f);

    // 2) scores (split-A, causal block-skip): (Qh+Ql)·Kh^T  (scale pre-folded in Q)
    dim3 gS(Sd/128, Sd/128, BHd);
    tc_gemm<EPI_SC><<<gS, blk, GSMEM>>>(qh, ql, kh, sp, nullptr, nullptr,
                                        HDd, HDd, HDd,
                                        (long long)Sd*HDd, (long long)Sd*HDd);

    // 3) softmax
    softmax_kernel<<<dim3(Sd, BHd), 256>>>(sp, pph, ppl);

    // 4) P · V (split-A, k-clamped), via V^T hi
    dim3 gAV(1, Sd/128, BHd);
    tc_gemm<EPI_AV><<<gAV, blk, GSMEM>>>(pph, ppl, vth, nullptr, omh, oml,
                                         Sd, Sd, Sd,
                                         (long long)Sd*Sd, (long long)HDd*Sd);

    // 5) output projection (split-B) -> fp32 out
    dim3 gO(Dd/256, Md/128, 1);
    tc_gemm_w<EPI_OUT><<<gO, blk, GSMEM2>>>(omh, woh, wol, out, nullptr, nullptr, Dd, Dd, Dd, 1.0f);
}